// round 1
// baseline (speedup 1.0000x reference)
#include <cuda_runtime.h>
#include <math.h>

#define B_     4
#define L_     8192
#define C_     1024
#define H_     16
#define D_     64
#define LCTX   256
#define WSZ    256
#define SHIFT_ 128
#define MLP_   4096
#define BL_    (B_ * L_)   // 32768
#define SIXC   (6 * C_)

// ---------------------------------------------------------------------------
// Scratch (device globals: allocation-free rule)
// ---------------------------------------------------------------------------
__device__ float g_scratch_a[(size_t)BL_ * MLP_];   // qkv (3C) / q (C) / mlp hidden (4C)
__device__ float g_scratch_h[(size_t)BL_ * C_];     // LN outputs / attention outputs
__device__ float g_mbuf[B_ * SIXC];                 // modulation vectors
__device__ float g_kvbuf[B_ * LCTX * 2 * C_];       // cross-attn K,V

// ---------------------------------------------------------------------------
// Small GEMM: m = silu(mod) @ mod_w + mod_b      (4 x 1024) @ (1024 x 6144)
// ---------------------------------------------------------------------------
__global__ void __launch_bounds__(256) mod_gemm_kernel(
    const float* __restrict__ mod, const float* __restrict__ W,
    const float* __restrict__ bias, float* __restrict__ out)
{
    int b = blockIdx.y;
    int n = blockIdx.x * 256 + threadIdx.x;
    __shared__ float sa[C_];
    for (int k = threadIdx.x; k < C_; k += 256) {
        float v = mod[b * C_ + k];
        sa[k] = v / (1.0f + expf(-v));   // silu
    }
    __syncthreads();
    float acc = bias[n];
#pragma unroll 8
    for (int k = 0; k < C_; k++)
        acc += sa[k] * W[(size_t)k * SIXC + n];
    out[b * SIXC + n] = acc;
}

// ---------------------------------------------------------------------------
// LayerNorm + affine/modulation:
//   out = (x - mu) * rstd * (sadd + scale[b*bstride + c]) + shift[b*bstride + c]
// one block per row (1024 elems), 256 threads x float4
// ---------------------------------------------------------------------------
__global__ void __launch_bounds__(256) ln_kernel(
    const float* __restrict__ x, float* __restrict__ out,
    const float* __restrict__ scale, const float* __restrict__ shift,
    int bstride, float sadd)
{
    int row = blockIdx.x;
    int b = row >> 13;                       // row / 8192
    const float4* xr = (const float4*)(x + (size_t)row * C_);
    float4 v = xr[threadIdx.x];
    float s  = v.x + v.y + v.z + v.w;
    float sq = v.x * v.x + v.y * v.y + v.z * v.z + v.w * v.w;
#pragma unroll
    for (int o = 16; o > 0; o >>= 1) {
        s  += __shfl_xor_sync(0xffffffffu, s,  o);
        sq += __shfl_xor_sync(0xffffffffu, sq, o);
    }
    __shared__ float rs[8], rq[8];
    int warp = threadIdx.x >> 5, lane = threadIdx.x & 31;
    if (lane == 0) { rs[warp] = s; rq[warp] = sq; }
    __syncthreads();
    s = 0.0f; sq = 0.0f;
#pragma unroll
    for (int i = 0; i < 8; i++) { s += rs[i]; sq += rq[i]; }
    float mean = s * (1.0f / C_);
    float var  = sq * (1.0f / C_) - mean * mean;
    float rstd = rsqrtf(var + 1e-6f);

    int c = threadIdx.x << 2;
    const float4 g = *(const float4*)(scale + b * bstride + c);
    const float4 t = *(const float4*)(shift + b * bstride + c);
    float4 o4;
    o4.x = (v.x - mean) * rstd * (sadd + g.x) + t.x;
    o4.y = (v.y - mean) * rstd * (sadd + g.y) + t.y;
    o4.z = (v.z - mean) * rstd * (sadd + g.z) + t.z;
    o4.w = (v.w - mean) * rstd * (sadd + g.w) + t.w;
    ((float4*)(out + (size_t)row * C_))[threadIdx.x] = o4;
}

// ---------------------------------------------------------------------------
// SGEMM: C = epilogue(A[MxK] @ B[KxN] + bias)
// 128x128 block tile, BK=16, 256 threads, 8x8 per thread, double-buffered smem
// MODE 0: +bias    1: gelu(+bias)    2: resid + (+bias)    3: resid + (+bias)*gate
// Requires M%128==0, N%128==0, K%16==0 (all shapes here satisfy this)
// ---------------------------------------------------------------------------
__device__ __forceinline__ float gelu_tanh(float v)
{
    float v3 = v * v * v;
    float t = tanhf(0.7978845608028654f * (v + 0.044715f * v3));
    return 0.5f * v * (1.0f + t);
}

template <int MODE>
__global__ void __launch_bounds__(256, 2) sgemm_kernel(
    const float* __restrict__ A, const float* __restrict__ Bw,
    const float* __restrict__ bias, const float* __restrict__ resid,
    const float* __restrict__ gate, float* __restrict__ C,
    int M, int N, int K, int gstride)
{
    __shared__ __align__(16) float As[2][16][132];
    __shared__ __align__(16) float Bs[2][16][132];

    int tid = threadIdx.x;
    int bm = blockIdx.y * 128;
    int bn = blockIdx.x * 128;

    int ar = tid >> 2;           // 0..63  (rows ar, ar+64)
    int ac = (tid & 3) << 2;     // k-offset 0,4,8,12
    int br = tid >> 5;           // 0..7   (rows br, br+8)
    int bc = (tid & 31) << 2;    // col offset 0..124

    const float* Ap = A + (size_t)bm * K;
    const float* Bp = Bw + bn;

    float4 a0, a1, b0, b1;
    a0 = *(const float4*)(Ap + (size_t)ar * K + ac);
    a1 = *(const float4*)(Ap + (size_t)(ar + 64) * K + ac);
    b0 = *(const float4*)(Bp + (size_t)br * N + bc);
    b1 = *(const float4*)(Bp + (size_t)(br + 8) * N + bc);

    As[0][ac + 0][ar] = a0.x; As[0][ac + 1][ar] = a0.y;
    As[0][ac + 2][ar] = a0.z; As[0][ac + 3][ar] = a0.w;
    As[0][ac + 0][ar + 64] = a1.x; As[0][ac + 1][ar + 64] = a1.y;
    As[0][ac + 2][ar + 64] = a1.z; As[0][ac + 3][ar + 64] = a1.w;
    *(float4*)&Bs[0][br][bc] = b0;
    *(float4*)&Bs[0][br + 8][bc] = b1;
    __syncthreads();

    int tx = tid & 15, ty = tid >> 4;
    float acc[8][8];
#pragma unroll
    for (int i = 0; i < 8; i++)
#pragma unroll
        for (int j = 0; j < 8; j++) acc[i][j] = 0.0f;

    int nk = K >> 4;
    for (int kt = 0; kt < nk; kt++) {
        int cur = kt & 1;
        if (kt + 1 < nk) {
            int k0 = (kt + 1) << 4;
            a0 = *(const float4*)(Ap + (size_t)ar * K + k0 + ac);
            a1 = *(const float4*)(Ap + (size_t)(ar + 64) * K + k0 + ac);
            b0 = *(const float4*)(Bp + (size_t)(k0 + br) * N + bc);
            b1 = *(const float4*)(Bp + (size_t)(k0 + br + 8) * N + bc);
        }
#pragma unroll
        for (int kk = 0; kk < 16; kk++) {
            float af[8], bf[8];
            *(float4*)&af[0] = *(const float4*)&As[cur][kk][ty * 8];
            *(float4*)&af[4] = *(const float4*)&As[cur][kk][ty * 8 + 4];
            *(float4*)&bf[0] = *(const float4*)&Bs[cur][kk][tx * 8];
            *(float4*)&bf[4] = *(const float4*)&Bs[cur][kk][tx * 8 + 4];
#pragma unroll
            for (int i = 0; i < 8; i++)
#pragma unroll
                for (int j = 0; j < 8; j++)
                    acc[i][j] += af[i] * bf[j];
        }
        if (kt + 1 < nk) {
            int nb = cur ^ 1;
            As[nb][ac + 0][ar] = a0.x; As[nb][ac + 1][ar] = a0.y;
            As[nb][ac + 2][ar] = a0.z; As[nb][ac + 3][ar] = a0.w;
            As[nb][ac + 0][ar + 64] = a1.x; As[nb][ac + 1][ar + 64] = a1.y;
            As[nb][ac + 2][ar + 64] = a1.z; As[nb][ac + 3][ar + 64] = a1.w;
            *(float4*)&Bs[nb][br][bc] = b0;
            *(float4*)&Bs[nb][br + 8][bc] = b1;
        }
        __syncthreads();
    }

    int row0 = bm + ty * 8;
    int col0 = bn + tx * 8;
#pragma unroll
    for (int i = 0; i < 8; i++) {
        int row = row0 + i;
        int bofs = (row >> 13) * gstride;
#pragma unroll
        for (int jj = 0; jj < 2; jj++) {
            int col = col0 + jj * 4;
            float4 bi = *(const float4*)(bias + col);
            float4 v;
            v.x = acc[i][jj * 4 + 0] + bi.x;
            v.y = acc[i][jj * 4 + 1] + bi.y;
            v.z = acc[i][jj * 4 + 2] + bi.z;
            v.w = acc[i][jj * 4 + 3] + bi.w;
            if (MODE == 1) {
                v.x = gelu_tanh(v.x); v.y = gelu_tanh(v.y);
                v.z = gelu_tanh(v.z); v.w = gelu_tanh(v.w);
            }
            if (MODE == 2) {
                float4 r = *(const float4*)(resid + (size_t)row * N + col);
                v.x += r.x; v.y += r.y; v.z += r.z; v.w += r.w;
            }
            if (MODE == 3) {
                float4 r = *(const float4*)(resid + (size_t)row * N + col);
                float4 gg = *(const float4*)(gate + bofs + col);
                v.x = r.x + v.x * gg.x; v.y = r.y + v.y * gg.y;
                v.z = r.z + v.z * gg.z; v.w = r.w + v.w * gg.w;
            }
            *(float4*)(C + (size_t)row * N + col) = v;
        }
    }
}

// ---------------------------------------------------------------------------
// Windowed self-attention. roll(-128) folded into indexing:
// window w covers original positions s = (w*256 + r + 128) & 8191, output
// written back at s (which is exactly roll(+128) of the rolled output).
// One block = (head, window, batch); one thread = one query row.
// K,V tiles (256x64 fp32 each) in 128KB dynamic smem.
// ---------------------------------------------------------------------------
__global__ void __launch_bounds__(256, 1) wattn_kernel(
    const float* __restrict__ qkv, float* __restrict__ o)
{
    extern __shared__ __align__(16) float smem[];
    float* s_k = smem;               // 256*64
    float* s_v = smem + 256 * 64;    // 256*64
    int h = blockIdx.x, w = blockIdx.y, b = blockIdx.z;
    int t = threadIdx.x;
    const size_t base = (size_t)b * L_ * (3 * C_);

    float4* sk4 = (float4*)s_k;
    float4* sv4 = (float4*)s_v;
    for (int i = t; i < 256 * 16; i += 256) {
        int r = i >> 4, d4 = i & 15;
        int s = ((w << 8) + r + SHIFT_) & (L_ - 1);
        const float4* row = (const float4*)(qkv + base + (size_t)s * (3 * C_));
        sk4[i] = row[256 + (h << 4) + d4];   // K at offset C
        sv4[i] = row[512 + (h << 4) + d4];   // V at offset 2C
    }

    int sq = ((w << 8) + t + SHIFT_) & (L_ - 1);
    const float4* qrow = (const float4*)(qkv + base + (size_t)sq * (3 * C_) + h * D_);
    float q[64];
#pragma unroll
    for (int d4 = 0; d4 < 16; d4++) {
        float4 qq = qrow[d4];
        q[d4 * 4 + 0] = qq.x; q[d4 * 4 + 1] = qq.y;
        q[d4 * 4 + 2] = qq.z; q[d4 * 4 + 3] = qq.w;
    }
    __syncthreads();

    float mx = -1e30f, l = 0.0f;
    float oa[64];
#pragma unroll
    for (int d = 0; d < 64; d++) oa[d] = 0.0f;

    for (int k = 0; k < 256; k++) {
        const float4* kr = (const float4*)(s_k + (k << 6));
        float s = 0.0f;
#pragma unroll
        for (int d4 = 0; d4 < 16; d4++) {
            float4 kv4 = kr[d4];
            s += q[d4 * 4 + 0] * kv4.x + q[d4 * 4 + 1] * kv4.y
               + q[d4 * 4 + 2] * kv4.z + q[d4 * 4 + 3] * kv4.w;
        }
        s *= 0.125f;  // 1/sqrt(64)
        if (s > mx) {
            float c = __expf(mx - s);
            l *= c;
#pragma unroll
            for (int d = 0; d < 64; d++) oa[d] *= c;
            mx = s;
        }
        float p = __expf(s - mx);
        l += p;
        const float4* vr = (const float4*)(s_v + (k << 6));
#pragma unroll
        for (int d4 = 0; d4 < 16; d4++) {
            float4 vv = vr[d4];
            oa[d4 * 4 + 0] += p * vv.x; oa[d4 * 4 + 1] += p * vv.y;
            oa[d4 * 4 + 2] += p * vv.z; oa[d4 * 4 + 3] += p * vv.w;
        }
    }
    float inv = 1.0f / l;
    float4* orow = (float4*)(o + ((size_t)b * L_ + sq) * C_ + h * D_);
#pragma unroll
    for (int d4 = 0; d4 < 16; d4++) {
        float4 vv;
        vv.x = oa[d4 * 4 + 0] * inv; vv.y = oa[d4 * 4 + 1] * inv;
        vv.z = oa[d4 * 4 + 2] * inv; vv.w = oa[d4 * 4 + 3] * inv;
        orow[d4] = vv;
    }
}

// ---------------------------------------------------------------------------
// Cross-attention: Q (B,L,H,D) vs K,V (B,256,H,D) from g_kvbuf.
// One block = (qtile of 256, head, batch); one thread = one query.
// ---------------------------------------------------------------------------
__global__ void __launch_bounds__(256, 1) xattn_kernel(
    const float* __restrict__ q, const float* __restrict__ kv,
    float* __restrict__ o)
{
    extern __shared__ __align__(16) float smem[];
    float* s_k = smem;
    float* s_v = smem + 256 * 64;
    int h = blockIdx.y, b = blockIdx.z;
    int t = threadIdx.x;

    float4* sk4 = (float4*)s_k;
    float4* sv4 = (float4*)s_v;
    for (int i = t; i < 256 * 16; i += 256) {
        int r = i >> 4, d4 = i & 15;
        const float4* row = (const float4*)(kv + ((size_t)b * LCTX + r) * (2 * C_));
        sk4[i] = row[(h << 4) + d4];          // K at offset 0
        sv4[i] = row[256 + (h << 4) + d4];    // V at offset C
    }

    int pos = blockIdx.x * 256 + t;
    const float4* qrow = (const float4*)(q + ((size_t)b * L_ + pos) * C_ + h * D_);
    float qr[64];
#pragma unroll
    for (int d4 = 0; d4 < 16; d4++) {
        float4 qq = qrow[d4];
        qr[d4 * 4 + 0] = qq.x; qr[d4 * 4 + 1] = qq.y;
        qr[d4 * 4 + 2] = qq.z; qr[d4 * 4 + 3] = qq.w;
    }
    __syncthreads();

    float mx = -1e30f, l = 0.0f;
    float oa[64];
#pragma unroll
    for (int d = 0; d < 64; d++) oa[d] = 0.0f;

    for (int k = 0; k < 256; k++) {
        const float4* kr = (const float4*)(s_k + (k << 6));
        float s = 0.0f;
#pragma unroll
        for (int d4 = 0; d4 < 16; d4++) {
            float4 kv4 = kr[d4];
            s += qr[d4 * 4 + 0] * kv4.x + qr[d4 * 4 + 1] * kv4.y
               + qr[d4 * 4 + 2] * kv4.z + qr[d4 * 4 + 3] * kv4.w;
        }
        s *= 0.125f;
        if (s > mx) {
            float c = __expf(mx - s);
            l *= c;
#pragma unroll
            for (int d = 0; d < 64; d++) oa[d] *= c;
            mx = s;
        }
        float p = __expf(s - mx);
        l += p;
        const float4* vr = (const float4*)(s_v + (k << 6));
#pragma unroll
        for (int d4 = 0; d4 < 16; d4++) {
            float4 vv = vr[d4];
            oa[d4 * 4 + 0] += p * vv.x; oa[d4 * 4 + 1] += p * vv.y;
            oa[d4 * 4 + 2] += p * vv.z; oa[d4 * 4 + 3] += p * vv.w;
        }
    }
    float inv = 1.0f / l;
    float4* orow = (float4*)(o + ((size_t)b * L_ + pos) * C_ + h * D_);
#pragma unroll
    for (int d4 = 0; d4 < 16; d4++) {
        float4 vv;
        vv.x = oa[d4 * 4 + 0] * inv; vv.y = oa[d4 * 4 + 1] * inv;
        vv.z = oa[d4 * 4 + 2] * inv; vv.w = oa[d4 * 4 + 3] * inv;
        orow[d4] = vv;
    }
}

// ---------------------------------------------------------------------------
// Launch
// ---------------------------------------------------------------------------
extern "C" void kernel_launch(void* const* d_in, const int* in_sizes, int n_in,
                              void* d_out, int out_size)
{
    (void)in_sizes; (void)n_in; (void)out_size;
    const float* x     = (const float*)d_in[0];
    const float* mod   = (const float*)d_in[1];
    const float* ctx   = (const float*)d_in[2];
    const float* mod_w = (const float*)d_in[3];
    const float* mod_b = (const float*)d_in[4];
    const float* n2g   = (const float*)d_in[5];
    const float* n2b   = (const float*)d_in[6];
    const float* qkv_w = (const float*)d_in[7];
    const float* qkv_b = (const float*)d_in[8];
    const float* saow  = (const float*)d_in[9];
    const float* saob  = (const float*)d_in[10];
    const float* q_w   = (const float*)d_in[11];
    const float* q_b   = (const float*)d_in[12];
    const float* kv_w  = (const float*)d_in[13];
    const float* kv_b  = (const float*)d_in[14];
    const float* caow  = (const float*)d_in[15];
    const float* caob  = (const float*)d_in[16];
    const float* w1    = (const float*)d_in[17];
    const float* b1    = (const float*)d_in[18];
    const float* w2    = (const float*)d_in[19];
    const float* b2    = (const float*)d_in[20];
    float* out = (float*)d_out;

    float *sa_, *sh_, *m_, *kv_;
    cudaGetSymbolAddress((void**)&sa_, g_scratch_a);
    cudaGetSymbolAddress((void**)&sh_, g_scratch_h);
    cudaGetSymbolAddress((void**)&m_,  g_mbuf);
    cudaGetSymbolAddress((void**)&kv_, g_kvbuf);

    cudaFuncSetAttribute(wattn_kernel, cudaFuncAttributeMaxDynamicSharedMemorySize, 131072);
    cudaFuncSetAttribute(xattn_kernel, cudaFuncAttributeMaxDynamicSharedMemorySize, 131072);

    // 1. modulation vectors
    mod_gemm_kernel<<<dim3(24, 4), 256>>>(mod, mod_w, mod_b, m_);
    // 2. h = LN(x)*(1+sc_msa) + sh_msa
    ln_kernel<<<BL_, 256>>>(x, sh_, m_ + C_, m_, SIXC, 1.0f);
    // 3. qkv = h @ qkv_w + b
    sgemm_kernel<0><<<dim3(24, 256), 256>>>(sh_, qkv_w, qkv_b, nullptr, nullptr,
                                            sa_, BL_, 3 * C_, C_, 0);
    // 4. windowed self-attention (rolls folded in)
    wattn_kernel<<<dim3(16, 32, 4), 256, 131072>>>(sa_, sh_);
    // 5. out = x + (o @ sa_out_w + b) * g_msa
    sgemm_kernel<3><<<dim3(8, 256), 256>>>(sh_, saow, saob, x, m_ + 2 * C_,
                                           out, BL_, C_, C_, SIXC);
    // 6. h2 = LN(out)*norm2_g + norm2_b
    ln_kernel<<<BL_, 256>>>(out, sh_, n2g, n2b, 0, 0.0f);
    // 7. q = h2 @ q_w + b
    sgemm_kernel<0><<<dim3(8, 256), 256>>>(sh_, q_w, q_b, nullptr, nullptr,
                                           sa_, BL_, C_, C_, 0);
    // 8. kv = ctx @ kv_w + b
    sgemm_kernel<0><<<dim3(16, 8), 256>>>(ctx, kv_w, kv_b, nullptr, nullptr,
                                          kv_, B_ * LCTX, 2 * C_, C_, 0);
    // 9. cross-attention
    xattn_kernel<<<dim3(32, 16, 4), 256, 131072>>>(sa_, kv_, sh_);
    // 10. out += o @ ca_out_w + b
    sgemm_kernel<2><<<dim3(8, 256), 256>>>(sh_, caow, caob, out, nullptr,
                                           out, BL_, C_, C_, 0);
    // 11. h = LN(out)*(1+sc_mlp) + sh_mlp
    ln_kernel<<<BL_, 256>>>(out, sh_, m_ + 4 * C_, m_ + 3 * C_, SIXC, 1.0f);
    // 12. u = gelu(h @ w1 + b1)
    sgemm_kernel<1><<<dim3(32, 256), 256>>>(sh_, w1, b1, nullptr, nullptr,
                                            sa_, BL_, MLP_, C_, 0);
    // 13. out += (u @ w2 + b2) * g_mlp
    sgemm_kernel<3><<<dim3(8, 256), 256>>>(sa_, w2, b2, out, m_ + 5 * C_,
                                           out, BL_, C_, MLP_, SIXC);
}

// round 2
// speedup vs baseline: 1.9798x; 1.9798x over previous
#include <cuda_runtime.h>
#include <math.h>
#include <stdint.h>

#define B_     4
#define L_     8192
#define C_     1024
#define H_     16
#define D_     64
#define LCTX   256
#define WSZ    256
#define SHIFT_ 128
#define MLP_   4096
#define BL_    (B_ * L_)   // 32768
#define SIXC   (6 * C_)

// ---------------------------------------------------------------------------
// Scratch (device globals: allocation-free rule)
// ---------------------------------------------------------------------------
__device__ float g_scratch_a[(size_t)BL_ * MLP_];   // qkv (3C) / q (C) / mlp hidden (4C)
__device__ float g_scratch_h[(size_t)BL_ * C_];     // LN outputs / attention outputs
__device__ float g_mbuf[B_ * SIXC];                 // modulation vectors
__device__ float g_kvbuf[B_ * LCTX * 2 * C_];       // cross-attn K,V

// ---------------------------------------------------------------------------
// Small GEMM: m = silu(mod) @ mod_w + mod_b      (4 x 1024) @ (1024 x 6144)
// ---------------------------------------------------------------------------
__global__ void __launch_bounds__(256) mod_gemm_kernel(
    const float* __restrict__ mod, const float* __restrict__ W,
    const float* __restrict__ bias, float* __restrict__ out)
{
    int b = blockIdx.y;
    int n = blockIdx.x * 256 + threadIdx.x;
    __shared__ float sa[C_];
    for (int k = threadIdx.x; k < C_; k += 256) {
        float v = mod[b * C_ + k];
        sa[k] = v / (1.0f + expf(-v));   // silu
    }
    __syncthreads();
    float acc = bias[n];
#pragma unroll 8
    for (int k = 0; k < C_; k++)
        acc += sa[k] * W[(size_t)k * SIXC + n];
    out[b * SIXC + n] = acc;
}

// ---------------------------------------------------------------------------
// LayerNorm + affine/modulation
// ---------------------------------------------------------------------------
__global__ void __launch_bounds__(256) ln_kernel(
    const float* __restrict__ x, float* __restrict__ out,
    const float* __restrict__ scale, const float* __restrict__ shift,
    int bstride, float sadd)
{
    int row = blockIdx.x;
    int b = row >> 13;
    const float4* xr = (const float4*)(x + (size_t)row * C_);
    float4 v = xr[threadIdx.x];
    float s  = v.x + v.y + v.z + v.w;
    float sq = v.x * v.x + v.y * v.y + v.z * v.z + v.w * v.w;
#pragma unroll
    for (int o = 16; o > 0; o >>= 1) {
        s  += __shfl_xor_sync(0xffffffffu, s,  o);
        sq += __shfl_xor_sync(0xffffffffu, sq, o);
    }
    __shared__ float rs[8], rq[8];
    int warp = threadIdx.x >> 5, lane = threadIdx.x & 31;
    if (lane == 0) { rs[warp] = s; rq[warp] = sq; }
    __syncthreads();
    s = 0.0f; sq = 0.0f;
#pragma unroll
    for (int i = 0; i < 8; i++) { s += rs[i]; sq += rq[i]; }
    float mean = s * (1.0f / C_);
    float var  = sq * (1.0f / C_) - mean * mean;
    float rstd = rsqrtf(var + 1e-6f);

    int c = threadIdx.x << 2;
    const float4 g = *(const float4*)(scale + b * bstride + c);
    const float4 t = *(const float4*)(shift + b * bstride + c);
    float4 o4;
    o4.x = (v.x - mean) * rstd * (sadd + g.x) + t.x;
    o4.y = (v.y - mean) * rstd * (sadd + g.y) + t.y;
    o4.z = (v.z - mean) * rstd * (sadd + g.z) + t.z;
    o4.w = (v.w - mean) * rstd * (sadd + g.w) + t.w;
    ((float4*)(out + (size_t)row * C_))[threadIdx.x] = o4;
}

// ---------------------------------------------------------------------------
// TF32 tensor-core GEMM: C = epilogue(A[MxK] @ B[KxN] + bias)
// 128x128 block tile, BK=32, 8 warps (2m x 4n), warp tile 64x32,
// mma.sync.m16n8k8.tf32, cp.async double-buffered smem.
// MODE 0: +bias   1: gelu(+bias)   2: resid+(+bias)   3: resid+(+bias)*gate
// Requires M%128==0, N%128==0, K%32==0.
// ---------------------------------------------------------------------------
__device__ __forceinline__ float gelu_tanh(float v)
{
    float v3 = v * v * v;
    float t = tanhf(0.7978845608028654f * (v + 0.044715f * v3));
    return 0.5f * v * (1.0f + t);
}

__device__ __forceinline__ uint32_t f2tf(float x)
{
    uint32_t u;
    asm("cvt.rna.tf32.f32 %0, %1;" : "=r"(u) : "f"(x));
    return u;
}

__device__ __forceinline__ void cpasync16(float* s, const float* g)
{
    uint32_t sa = (uint32_t)__cvta_generic_to_shared(s);
    asm volatile("cp.async.cg.shared.global [%0], [%1], 16;\n" :: "r"(sa), "l"(g));
}

#define A_PAD 36     // As[128][36]
#define B_PAD 136    // Bs[32][136]
#define A_SZ  (128 * A_PAD)
#define B_SZ  (32 * B_PAD)
#define STG_SZ (A_SZ + B_SZ)

template <int MODE>
__global__ void __launch_bounds__(256) tgemm_kernel(
    const float* __restrict__ A, const float* __restrict__ Bw,
    const float* __restrict__ bias, const float* __restrict__ resid,
    const float* __restrict__ gate, float* __restrict__ C,
    int M, int N, int K, int gstride)
{
    extern __shared__ __align__(16) float smem[];

    int tid = threadIdx.x;
    int bm = blockIdx.y * 128;
    int bn = blockIdx.x * 128;

    int lane = tid & 31;
    int wid  = tid >> 5;
    int wm = (wid & 1) * 64;     // warp m offset
    int wn = (wid >> 1) * 32;    // warp n offset
    int r = lane >> 2, c = lane & 3;

    // cp.async source mapping
    int arow = tid >> 1;              // 0..127
    int acol = (tid & 1) * 16;        // 0 or 16
    int brow = tid >> 3;              // 0..31
    int bcol = (tid & 7) * 16;        // 0..112

    const float* Ag = A + (size_t)(bm + arow) * K + acol;
    const float* Bg = Bw + (size_t)brow * N + bn + bcol;

    float acc[4][4][4];
#pragma unroll
    for (int mi = 0; mi < 4; mi++)
#pragma unroll
        for (int ni = 0; ni < 4; ni++)
#pragma unroll
            for (int q = 0; q < 4; q++) acc[mi][ni][q] = 0.0f;

    // prefetch stage 0
    {
        float* As = smem;
        float* Bs = smem + A_SZ;
        float* as = As + arow * A_PAD + acol;
        float* bs = Bs + brow * B_PAD + bcol;
#pragma unroll
        for (int i = 0; i < 4; i++) cpasync16(as + i * 4, Ag + i * 4);
#pragma unroll
        for (int i = 0; i < 4; i++) cpasync16(bs + i * 4, Bg + i * 4);
        asm volatile("cp.async.commit_group;\n" ::);
    }

    int nk = K >> 5;
    for (int kt = 0; kt < nk; kt++) {
        int cur = kt & 1;
        if (kt + 1 < nk) {
            int k0n = (kt + 1) << 5;
            float* As = smem + (cur ^ 1) * STG_SZ;
            float* Bs = As + A_SZ;
            float* as = As + arow * A_PAD + acol;
            float* bs = Bs + brow * B_PAD + bcol;
#pragma unroll
            for (int i = 0; i < 4; i++) cpasync16(as + i * 4, Ag + k0n + i * 4);
#pragma unroll
            for (int i = 0; i < 4; i++) cpasync16(bs + i * 4, Bg + (size_t)k0n * N + i * 4);
            asm volatile("cp.async.commit_group;\n" ::);
            asm volatile("cp.async.wait_group 1;\n" ::);
        } else {
            asm volatile("cp.async.wait_group 0;\n" ::);
        }
        __syncthreads();

        const float* As = smem + cur * STG_SZ;
        const float* Bs = As + A_SZ;

#pragma unroll
        for (int ks = 0; ks < 4; ks++) {
            int k0 = ks << 3;
            uint32_t af[4][4], bf[4][2];
#pragma unroll
            for (int mi = 0; mi < 4; mi++) {
                const float* p = As + (wm + mi * 16 + r) * A_PAD + k0 + c;
                af[mi][0] = f2tf(p[0]);
                af[mi][1] = f2tf(p[8 * A_PAD]);
                af[mi][2] = f2tf(p[4]);
                af[mi][3] = f2tf(p[8 * A_PAD + 4]);
            }
#pragma unroll
            for (int ni = 0; ni < 4; ni++) {
                const float* p = Bs + (k0 + c) * B_PAD + wn + ni * 8 + r;
                bf[ni][0] = f2tf(p[0]);
                bf[ni][1] = f2tf(p[4 * B_PAD]);
            }
#pragma unroll
            for (int mi = 0; mi < 4; mi++)
#pragma unroll
                for (int ni = 0; ni < 4; ni++) {
                    asm volatile(
                        "mma.sync.aligned.m16n8k8.row.col.f32.tf32.tf32.f32 "
                        "{%0,%1,%2,%3}, {%4,%5,%6,%7}, {%8,%9}, {%0,%1,%2,%3};\n"
                        : "+f"(acc[mi][ni][0]), "+f"(acc[mi][ni][1]),
                          "+f"(acc[mi][ni][2]), "+f"(acc[mi][ni][3])
                        : "r"(af[mi][0]), "r"(af[mi][1]), "r"(af[mi][2]), "r"(af[mi][3]),
                          "r"(bf[ni][0]), "r"(bf[ni][1]));
                }
        }
        __syncthreads();
    }

    // epilogue
#pragma unroll
    for (int mi = 0; mi < 4; mi++) {
#pragma unroll
        for (int r2 = 0; r2 < 2; r2++) {
            int row = bm + wm + mi * 16 + r + r2 * 8;
            int bofs = (row >> 13) * gstride;
#pragma unroll
            for (int ni = 0; ni < 4; ni++) {
                int col = bn + wn + ni * 8 + 2 * c;
                float2 bi = *(const float2*)(bias + col);
                float2 v;
                v.x = acc[mi][ni][r2 * 2 + 0] + bi.x;
                v.y = acc[mi][ni][r2 * 2 + 1] + bi.y;
                if (MODE == 1) {
                    v.x = gelu_tanh(v.x); v.y = gelu_tanh(v.y);
                }
                if (MODE == 2) {
                    float2 rr = *(const float2*)(resid + (size_t)row * N + col);
                    v.x += rr.x; v.y += rr.y;
                }
                if (MODE == 3) {
                    float2 rr = *(const float2*)(resid + (size_t)row * N + col);
                    float2 gg = *(const float2*)(gate + bofs + col);
                    v.x = rr.x + v.x * gg.x;
                    v.y = rr.y + v.y * gg.y;
                }
                *(float2*)(C + (size_t)row * N + col) = v;
            }
        }
    }
}

// ---------------------------------------------------------------------------
// Windowed self-attention (rolls folded into indexing)
// ---------------------------------------------------------------------------
__global__ void __launch_bounds__(256, 1) wattn_kernel(
    const float* __restrict__ qkv, float* __restrict__ o)
{
    extern __shared__ __align__(16) float smem[];
    float* s_k = smem;               // 256*64
    float* s_v = smem + 256 * 64;    // 256*64
    int h = blockIdx.x, w = blockIdx.y, b = blockIdx.z;
    int t = threadIdx.x;
    const size_t base = (size_t)b * L_ * (3 * C_);

    float4* sk4 = (float4*)s_k;
    float4* sv4 = (float4*)s_v;
    for (int i = t; i < 256 * 16; i += 256) {
        int rr = i >> 4, d4 = i & 15;
        int s = ((w << 8) + rr + SHIFT_) & (L_ - 1);
        const float4* row = (const float4*)(qkv + base + (size_t)s * (3 * C_));
        sk4[i] = row[256 + (h << 4) + d4];
        sv4[i] = row[512 + (h << 4) + d4];
    }

    int sq = ((w << 8) + t + SHIFT_) & (L_ - 1);
    const float4* qrow = (const float4*)(qkv + base + (size_t)sq * (3 * C_) + h * D_);
    float q[64];
#pragma unroll
    for (int d4 = 0; d4 < 16; d4++) {
        float4 qq = qrow[d4];
        q[d4 * 4 + 0] = qq.x; q[d4 * 4 + 1] = qq.y;
        q[d4 * 4 + 2] = qq.z; q[d4 * 4 + 3] = qq.w;
    }
    __syncthreads();

    float mx = -1e30f, l = 0.0f;
    float oa[64];
#pragma unroll
    for (int d = 0; d < 64; d++) oa[d] = 0.0f;

    for (int k = 0; k < 256; k++) {
        const float4* kr = (const float4*)(s_k + (k << 6));
        float s = 0.0f;
#pragma unroll
        for (int d4 = 0; d4 < 16; d4++) {
            float4 kv4 = kr[d4];
            s += q[d4 * 4 + 0] * kv4.x + q[d4 * 4 + 1] * kv4.y
               + q[d4 * 4 + 2] * kv4.z + q[d4 * 4 + 3] * kv4.w;
        }
        s *= 0.125f;
        if (s > mx) {
            float cc = __expf(mx - s);
            l *= cc;
#pragma unroll
            for (int d = 0; d < 64; d++) oa[d] *= cc;
            mx = s;
        }
        float p = __expf(s - mx);
        l += p;
        const float4* vr = (const float4*)(s_v + (k << 6));
#pragma unroll
        for (int d4 = 0; d4 < 16; d4++) {
            float4 vv = vr[d4];
            oa[d4 * 4 + 0] += p * vv.x; oa[d4 * 4 + 1] += p * vv.y;
            oa[d4 * 4 + 2] += p * vv.z; oa[d4 * 4 + 3] += p * vv.w;
        }
    }
    float inv = 1.0f / l;
    float4* orow = (float4*)(o + ((size_t)b * L_ + sq) * C_ + h * D_);
#pragma unroll
    for (int d4 = 0; d4 < 16; d4++) {
        float4 vv;
        vv.x = oa[d4 * 4 + 0] * inv; vv.y = oa[d4 * 4 + 1] * inv;
        vv.z = oa[d4 * 4 + 2] * inv; vv.w = oa[d4 * 4 + 3] * inv;
        orow[d4] = vv;
    }
}

// ---------------------------------------------------------------------------
// Cross-attention
// ---------------------------------------------------------------------------
__global__ void __launch_bounds__(256, 1) xattn_kernel(
    const float* __restrict__ q, const float* __restrict__ kv,
    float* __restrict__ o)
{
    extern __shared__ __align__(16) float smem[];
    float* s_k = smem;
    float* s_v = smem + 256 * 64;
    int h = blockIdx.y, b = blockIdx.z;
    int t = threadIdx.x;

    float4* sk4 = (float4*)s_k;
    float4* sv4 = (float4*)s_v;
    for (int i = t; i < 256 * 16; i += 256) {
        int rr = i >> 4, d4 = i & 15;
        const float4* row = (const float4*)(kv + ((size_t)b * LCTX + rr) * (2 * C_));
        sk4[i] = row[(h << 4) + d4];
        sv4[i] = row[256 + (h << 4) + d4];
    }

    int pos = blockIdx.x * 256 + t;
    const float4* qrow = (const float4*)(q + ((size_t)b * L_ + pos) * C_ + h * D_);
    float qr[64];
#pragma unroll
    for (int d4 = 0; d4 < 16; d4++) {
        float4 qq = qrow[d4];
        qr[d4 * 4 + 0] = qq.x; qr[d4 * 4 + 1] = qq.y;
        qr[d4 * 4 + 2] = qq.z; qr[d4 * 4 + 3] = qq.w;
    }
    __syncthreads();

    float mx = -1e30f, l = 0.0f;
    float oa[64];
#pragma unroll
    for (int d = 0; d < 64; d++) oa[d] = 0.0f;

    for (int k = 0; k < 256; k++) {
        const float4* kr = (const float4*)(s_k + (k << 6));
        float s = 0.0f;
#pragma unroll
        for (int d4 = 0; d4 < 16; d4++) {
            float4 kv4 = kr[d4];
            s += qr[d4 * 4 + 0] * kv4.x + qr[d4 * 4 + 1] * kv4.y
               + qr[d4 * 4 + 2] * kv4.z + qr[d4 * 4 + 3] * kv4.w;
        }
        s *= 0.125f;
        if (s > mx) {
            float cc = __expf(mx - s);
            l *= cc;
#pragma unroll
            for (int d = 0; d < 64; d++) oa[d] *= cc;
            mx = s;
        }
        float p = __expf(s - mx);
        l += p;
        const float4* vr = (const float4*)(s_v + (k << 6));
#pragma unroll
        for (int d4 = 0; d4 < 16; d4++) {
            float4 vv = vr[d4];
            oa[d4 * 4 + 0] += p * vv.x; oa[d4 * 4 + 1] += p * vv.y;
            oa[d4 * 4 + 2] += p * vv.z; oa[d4 * 4 + 3] += p * vv.w;
        }
    }
    float inv = 1.0f / l;
    float4* orow = (float4*)(o + ((size_t)b * L_ + pos) * C_ + h * D_);
#pragma unroll
    for (int d4 = 0; d4 < 16; d4++) {
        float4 vv;
        vv.x = oa[d4 * 4 + 0] * inv; vv.y = oa[d4 * 4 + 1] * inv;
        vv.z = oa[d4 * 4 + 2] * inv; vv.w = oa[d4 * 4 + 3] * inv;
        orow[d4] = vv;
    }
}

// ---------------------------------------------------------------------------
// Launch
// ---------------------------------------------------------------------------
#define TG_SMEM (2 * STG_SZ * 4)   // 71680 bytes

extern "C" void kernel_launch(void* const* d_in, const int* in_sizes, int n_in,
                              void* d_out, int out_size)
{
    (void)in_sizes; (void)n_in; (void)out_size;
    const float* x     = (const float*)d_in[0];
    const float* mod   = (const float*)d_in[1];
    const float* ctx   = (const float*)d_in[2];
    const float* mod_w = (const float*)d_in[3];
    const float* mod_b = (const float*)d_in[4];
    const float* n2g   = (const float*)d_in[5];
    const float* n2b   = (const float*)d_in[6];
    const float* qkv_w = (const float*)d_in[7];
    const float* qkv_b = (const float*)d_in[8];
    const float* saow  = (const float*)d_in[9];
    const float* saob  = (const float*)d_in[10];
    const float* q_w   = (const float*)d_in[11];
    const float* q_b   = (const float*)d_in[12];
    const float* kv_w  = (const float*)d_in[13];
    const float* kv_b  = (const float*)d_in[14];
    const float* caow  = (const float*)d_in[15];
    const float* caob  = (const float*)d_in[16];
    const float* w1    = (const float*)d_in[17];
    const float* b1    = (const float*)d_in[18];
    const float* w2    = (const float*)d_in[19];
    const float* b2    = (const float*)d_in[20];
    float* out = (float*)d_out;

    float *sa_, *sh_, *m_, *kv_;
    cudaGetSymbolAddress((void**)&sa_, g_scratch_a);
    cudaGetSymbolAddress((void**)&sh_, g_scratch_h);
    cudaGetSymbolAddress((void**)&m_,  g_mbuf);
    cudaGetSymbolAddress((void**)&kv_, g_kvbuf);

    cudaFuncSetAttribute(wattn_kernel, cudaFuncAttributeMaxDynamicSharedMemorySize, 131072);
    cudaFuncSetAttribute(xattn_kernel, cudaFuncAttributeMaxDynamicSharedMemorySize, 131072);
    cudaFuncSetAttribute(tgemm_kernel<0>, cudaFuncAttributeMaxDynamicSharedMemorySize, TG_SMEM);
    cudaFuncSetAttribute(tgemm_kernel<1>, cudaFuncAttributeMaxDynamicSharedMemorySize, TG_SMEM);
    cudaFuncSetAttribute(tgemm_kernel<2>, cudaFuncAttributeMaxDynamicSharedMemorySize, TG_SMEM);
    cudaFuncSetAttribute(tgemm_kernel<3>, cudaFuncAttributeMaxDynamicSharedMemorySize, TG_SMEM);

    // 1. modulation vectors
    mod_gemm_kernel<<<dim3(24, 4), 256>>>(mod, mod_w, mod_b, m_);
    // 2. h = LN(x)*(1+sc_msa) + sh_msa
    ln_kernel<<<BL_, 256>>>(x, sh_, m_ + C_, m_, SIXC, 1.0f);
    // 3. qkv = h @ qkv_w + b
    tgemm_kernel<0><<<dim3(24, 256), 256, TG_SMEM>>>(sh_, qkv_w, qkv_b, nullptr, nullptr,
                                                     sa_, BL_, 3 * C_, C_, 0);
    // 4. windowed self-attention
    wattn_kernel<<<dim3(16, 32, 4), 256, 131072>>>(sa_, sh_);
    // 5. out = x + (o @ sa_out_w + b) * g_msa
    tgemm_kernel<3><<<dim3(8, 256), 256, TG_SMEM>>>(sh_, saow, saob, x, m_ + 2 * C_,
                                                    out, BL_, C_, C_, SIXC);
    // 6. h2 = LN(out)*norm2_g + norm2_b
    ln_kernel<<<BL_, 256>>>(out, sh_, n2g, n2b, 0, 0.0f);
    // 7. q = h2 @ q_w + b
    tgemm_kernel<0><<<dim3(8, 256), 256, TG_SMEM>>>(sh_, q_w, q_b, nullptr, nullptr,
                                                    sa_, BL_, C_, C_, 0);
    // 8. kv = ctx @ kv_w + b
    tgemm_kernel<0><<<dim3(16, 8), 256, TG_SMEM>>>(ctx, kv_w, kv_b, nullptr, nullptr,
                                                   kv_, B_ * LCTX, 2 * C_, C_, 0);
    // 9. cross-attention
    xattn_kernel<<<dim3(32, 16, 4), 256, 131072>>>(sa_, kv_, sh_);
    // 10. out += o @ ca_out_w + b
    tgemm_kernel<2><<<dim3(8, 256), 256, TG_SMEM>>>(sh_, caow, caob, out, nullptr,
                                                    out, BL_, C_, C_, 0);
    // 11. h = LN(out)*(1+sc_mlp) + sh_mlp
    ln_kernel<<<BL_, 256>>>(out, sh_, m_ + 4 * C_, m_ + 3 * C_, SIXC, 1.0f);
    // 12. u = gelu(h @ w1 + b1)
    tgemm_kernel<1><<<dim3(32, 256), 256, TG_SMEM>>>(sh_, w1, b1, nullptr, nullptr,
                                                     sa_, BL_, MLP_, C_, 0);
    // 13. out += (u @ w2 + b2) * g_mlp
    tgemm_kernel<3><<<dim3(8, 256), 256, TG_SMEM>>>(sa_, w2, b2, out, m_ + 5 * C_,
                                                    out, BL_, C_, MLP_, SIXC);
}

// round 4
// speedup vs baseline: 3.7605x; 1.8995x over previous
#include <cuda_runtime.h>
#include <cuda_bf16.h>
#include <math.h>
#include <stdint.h>

#define B_     4
#define L_     8192
#define C_     1024
#define H_     16
#define D_     64
#define LCTX   256
#define SHIFT_ 128
#define MLP_   4096
#define BL_    (B_ * L_)   // 32768
#define SIXC   (6 * C_)

typedef __nv_bfloat16 bf16;
typedef __nv_bfloat162 bf162;

// single shared-memory symbol, cast per kernel
extern __shared__ __align__(16) char dsmem[];

// ---------------------------------------------------------------------------
// Scratch (device globals)
// ---------------------------------------------------------------------------
__device__ float g_scratch_a[(size_t)BL_ * MLP_];     // bf16 views: qkv/q + mlp hidden
__device__ float g_scratch_h[(size_t)BL_ * C_];       // bf16 view: LN / attn outputs
__device__ float g_mbuf[B_ * SIXC];                   // modulation vectors (fp32)
__device__ float g_kvbuf[B_ * LCTX * 2 * C_];         // bf16 view: cross-attn K,V
__device__ bf16  g_wbuf[17825792 + 1024];             // converted weights + ctx

// ---------------------------------------------------------------------------
// fp32 -> bf16 conversion
// ---------------------------------------------------------------------------
__global__ void __launch_bounds__(256) f2b_kernel(
    const float* __restrict__ in, bf16* __restrict__ out, int n)
{
    int i = (blockIdx.x * 256 + threadIdx.x) * 4;
    if (i < n) {
        float4 v = *(const float4*)(in + i);
        *(bf162*)(out + i)     = __floats2bfloat162_rn(v.x, v.y);
        *(bf162*)(out + i + 2) = __floats2bfloat162_rn(v.z, v.w);
    }
}

// ---------------------------------------------------------------------------
// Small GEMM: m = silu(mod) @ mod_w + mod_b  (fp32)
// ---------------------------------------------------------------------------
__global__ void __launch_bounds__(256) mod_gemm_kernel(
    const float* __restrict__ mod, const float* __restrict__ W,
    const float* __restrict__ bias, float* __restrict__ out)
{
    int b = blockIdx.y;
    int n = blockIdx.x * 256 + threadIdx.x;
    __shared__ float sa[C_];
    for (int k = threadIdx.x; k < C_; k += 256) {
        float v = mod[b * C_ + k];
        sa[k] = v / (1.0f + expf(-v));
    }
    __syncthreads();
    float acc = bias[n];
#pragma unroll 8
    for (int k = 0; k < C_; k++)
        acc += sa[k] * W[(size_t)k * SIXC + n];
    out[b * SIXC + n] = acc;
}

// ---------------------------------------------------------------------------
// LayerNorm + modulation, bf16 output
// ---------------------------------------------------------------------------
__global__ void __launch_bounds__(256) ln_kernel(
    const float* __restrict__ x, bf16* __restrict__ out,
    const float* __restrict__ scale, const float* __restrict__ shift,
    int bstride, float sadd)
{
    int row = blockIdx.x;
    int b = row >> 13;
    const float4* xr = (const float4*)(x + (size_t)row * C_);
    float4 v = xr[threadIdx.x];
    float s  = v.x + v.y + v.z + v.w;
    float sq = v.x * v.x + v.y * v.y + v.z * v.z + v.w * v.w;
#pragma unroll
    for (int o = 16; o > 0; o >>= 1) {
        s  += __shfl_xor_sync(0xffffffffu, s,  o);
        sq += __shfl_xor_sync(0xffffffffu, sq, o);
    }
    __shared__ float rs[8], rq[8];
    int warp = threadIdx.x >> 5, lane = threadIdx.x & 31;
    if (lane == 0) { rs[warp] = s; rq[warp] = sq; }
    __syncthreads();
    s = 0.0f; sq = 0.0f;
#pragma unroll
    for (int i = 0; i < 8; i++) { s += rs[i]; sq += rq[i]; }
    float mean = s * (1.0f / C_);
    float var  = sq * (1.0f / C_) - mean * mean;
    float rstd = rsqrtf(var + 1e-6f);

    int c = threadIdx.x << 2;
    const float4 g = *(const float4*)(scale + b * bstride + c);
    const float4 t = *(const float4*)(shift + b * bstride + c);
    float ox = (v.x - mean) * rstd * (sadd + g.x) + t.x;
    float oy = (v.y - mean) * rstd * (sadd + g.y) + t.y;
    float oz = (v.z - mean) * rstd * (sadd + g.z) + t.z;
    float ow = (v.w - mean) * rstd * (sadd + g.w) + t.w;
    bf16* op = out + (size_t)row * C_ + c;
    *(bf162*)(op)     = __floats2bfloat162_rn(ox, oy);
    *(bf162*)(op + 2) = __floats2bfloat162_rn(oz, ow);
}

// ---------------------------------------------------------------------------
// bf16 tensor-core GEMM: C = epilogue(A[MxK] @ B[KxN] + bias)
// 128x128 tile, BK=32, 8 warps (2x4), warp 64x32, mma.m16n8k16.bf16,
// 3-stage cp.async pipeline, ldmatrix fragment loads.
// MODE 0:+bias  1:gelu(+bias)  2:resid+  3:resid+*gate ; OUTB: bf16 output
// ---------------------------------------------------------------------------
__device__ __forceinline__ float gelu_tanh(float v)
{
    float v3 = v * v * v;
    float t = tanhf(0.7978845608028654f * (v + 0.044715f * v3));
    return 0.5f * v * (1.0f + t);
}

__device__ __forceinline__ void cpasync16(bf16* s, const bf16* g)
{
    uint32_t sa = (uint32_t)__cvta_generic_to_shared(s);
    asm volatile("cp.async.cg.shared.global [%0], [%1], 16;\n" :: "r"(sa), "l"(g));
}

#define BK     32
#define APAD   40      // bf16 per A row
#define BPAD   136     // bf16 per B row
#define ASZ    (128 * APAD)
#define BSZ    (BK * BPAD)
#define STG    (ASZ + BSZ)
#define NSTAGE 3
#define TG_SMEM (NSTAGE * STG * 2)   // 56832 bytes

template <int MODE, int OUTB>
__global__ void __launch_bounds__(256) tgemm_kernel(
    const bf16* __restrict__ A, const bf16* __restrict__ Bw,
    const float* __restrict__ bias, const float* __restrict__ resid,
    const float* __restrict__ gate, void* __restrict__ Cout,
    int M, int N, int K, int gstride)
{
    bf16* smem = (bf16*)dsmem;

    int tid = threadIdx.x;
    int bm = blockIdx.y * 128;
    int bn = blockIdx.x * 128;
    int lane = tid & 31;
    int wid  = tid >> 5;
    int wm = (wid & 1) * 64;
    int wn = (wid >> 1) * 32;

    // cp.async mapping
    int arow = tid >> 1;
    int acol = (tid & 1) * 16;
    int brow = tid >> 3;
    int bcol = (tid & 7) * 16;
    const bf16* Ag = A + (size_t)(bm + arow) * K + acol;
    const bf16* Bg = Bw + (size_t)brow * N + bn + bcol;

    float acc[4][4][4];
#pragma unroll
    for (int mi = 0; mi < 4; mi++)
#pragma unroll
        for (int ni = 0; ni < 4; ni++)
#pragma unroll
            for (int q = 0; q < 4; q++) acc[mi][ni][q] = 0.0f;

    int nk = K / BK;
    // prologue: stages 0..NSTAGE-2
#pragma unroll
    for (int s = 0; s < NSTAGE - 1; s++) {
        bf16* As = smem + s * STG;
        bf16* Bs = As + ASZ;
        int k0 = s * BK;
        cpasync16(As + arow * APAD + acol,     Ag + k0);
        cpasync16(As + arow * APAD + acol + 8, Ag + k0 + 8);
        cpasync16(Bs + brow * BPAD + bcol,     Bg + (size_t)k0 * N);
        cpasync16(Bs + brow * BPAD + bcol + 8, Bg + (size_t)k0 * N + 8);
        asm volatile("cp.async.commit_group;\n" ::);
    }

    for (int kt = 0; kt < nk; kt++) {
        int ldst = kt + NSTAGE - 1;
        if (ldst < nk) {
            bf16* As = smem + (ldst % NSTAGE) * STG;
            bf16* Bs = As + ASZ;
            int k0 = ldst * BK;
            cpasync16(As + arow * APAD + acol,     Ag + k0);
            cpasync16(As + arow * APAD + acol + 8, Ag + k0 + 8);
            cpasync16(Bs + brow * BPAD + bcol,     Bg + (size_t)k0 * N);
            cpasync16(Bs + brow * BPAD + bcol + 8, Bg + (size_t)k0 * N + 8);
        }
        asm volatile("cp.async.commit_group;\n" ::);
        asm volatile("cp.async.wait_group %0;\n" :: "n"(NSTAGE - 1));
        __syncthreads();

        const bf16* As = smem + (kt % NSTAGE) * STG;
        const bf16* Bs = As + ASZ;

#pragma unroll
        for (int ks = 0; ks < 2; ks++) {
            uint32_t af[4][4], bfr[2][4];
#pragma unroll
            for (int mi = 0; mi < 4; mi++) {
                uint32_t addr = (uint32_t)__cvta_generic_to_shared(
                    As + (wm + mi * 16 + (lane & 15)) * APAD + ks * 16 + (lane >> 4) * 8);
                asm volatile(
                    "ldmatrix.sync.aligned.m8n8.x4.shared.b16 {%0,%1,%2,%3}, [%4];\n"
                    : "=r"(af[mi][0]), "=r"(af[mi][1]), "=r"(af[mi][2]), "=r"(af[mi][3])
                    : "r"(addr));
            }
#pragma unroll
            for (int nh = 0; nh < 2; nh++) {
                uint32_t addr = (uint32_t)__cvta_generic_to_shared(
                    Bs + (ks * 16 + (lane & 15)) * BPAD + wn + nh * 16 + (lane >> 4) * 8);
                asm volatile(
                    "ldmatrix.sync.aligned.m8n8.x4.trans.shared.b16 {%0,%1,%2,%3}, [%4];\n"
                    : "=r"(bfr[nh][0]), "=r"(bfr[nh][1]), "=r"(bfr[nh][2]), "=r"(bfr[nh][3])
                    : "r"(addr));
            }
#pragma unroll
            for (int mi = 0; mi < 4; mi++)
#pragma unroll
                for (int ni = 0; ni < 4; ni++) {
                    asm volatile(
                        "mma.sync.aligned.m16n8k16.row.col.f32.bf16.bf16.f32 "
                        "{%0,%1,%2,%3}, {%4,%5,%6,%7}, {%8,%9}, {%0,%1,%2,%3};\n"
                        : "+f"(acc[mi][ni][0]), "+f"(acc[mi][ni][1]),
                          "+f"(acc[mi][ni][2]), "+f"(acc[mi][ni][3])
                        : "r"(af[mi][0]), "r"(af[mi][1]), "r"(af[mi][2]), "r"(af[mi][3]),
                          "r"(bfr[ni >> 1][(ni & 1) * 2]), "r"(bfr[ni >> 1][(ni & 1) * 2 + 1]));
                }
        }
        __syncthreads();
    }

    // epilogue
    int r = lane >> 2, c = lane & 3;
#pragma unroll
    for (int mi = 0; mi < 4; mi++) {
#pragma unroll
        for (int r2 = 0; r2 < 2; r2++) {
            int row = bm + wm + mi * 16 + r + r2 * 8;
            int bofs = (row >> 13) * gstride;
#pragma unroll
            for (int ni = 0; ni < 4; ni++) {
                int col = bn + wn + ni * 8 + 2 * c;
                float2 bi = *(const float2*)(bias + col);
                float vx = acc[mi][ni][r2 * 2 + 0] + bi.x;
                float vy = acc[mi][ni][r2 * 2 + 1] + bi.y;
                if (MODE == 1) { vx = gelu_tanh(vx); vy = gelu_tanh(vy); }
                if (MODE == 2) {
                    float2 rr = *(const float2*)(resid + (size_t)row * N + col);
                    vx += rr.x; vy += rr.y;
                }
                if (MODE == 3) {
                    float2 rr = *(const float2*)(resid + (size_t)row * N + col);
                    float2 gg = *(const float2*)(gate + bofs + col);
                    vx = rr.x + vx * gg.x;
                    vy = rr.y + vy * gg.y;
                }
                if (OUTB) {
                    *(bf162*)((bf16*)Cout + (size_t)row * N + col) =
                        __floats2bfloat162_rn(vx, vy);
                } else {
                    float2 v; v.x = vx; v.y = vy;
                    *(float2*)((float*)Cout + (size_t)row * N + col) = v;
                }
            }
        }
    }
}

// ---------------------------------------------------------------------------
// bf16x8 <-> float[8] helpers
// ---------------------------------------------------------------------------
__device__ __forceinline__ void bf8_to_f8(uint4 u, float* f)
{
    float2 a = __bfloat1622float2(*(bf162*)&u.x);
    float2 b = __bfloat1622float2(*(bf162*)&u.y);
    float2 c = __bfloat1622float2(*(bf162*)&u.z);
    float2 d = __bfloat1622float2(*(bf162*)&u.w);
    f[0] = a.x; f[1] = a.y; f[2] = b.x; f[3] = b.y;
    f[4] = c.x; f[5] = c.y; f[6] = d.x; f[7] = d.y;
}

__device__ __forceinline__ uint4 f8_to_bf8(const float* f)
{
    uint4 u;
    *(bf162*)&u.x = __floats2bfloat162_rn(f[0], f[1]);
    *(bf162*)&u.y = __floats2bfloat162_rn(f[2], f[3]);
    *(bf162*)&u.z = __floats2bfloat162_rn(f[4], f[5]);
    *(bf162*)&u.w = __floats2bfloat162_rn(f[6], f[7]);
    return u;
}

// ---------------------------------------------------------------------------
// Windowed self-attention (bf16 in/out, fp32 compute; rolls folded in)
// ---------------------------------------------------------------------------
__global__ void __launch_bounds__(256, 1) wattn_kernel(
    const bf16* __restrict__ qkv, bf16* __restrict__ o)
{
    float* smem = (float*)dsmem;
    float* s_k = smem;               // 256*64
    float* s_v = smem + 256 * 64;
    int h = blockIdx.x, w = blockIdx.y, b = blockIdx.z;
    int t = threadIdx.x;
    const size_t base = (size_t)b * L_ * (3 * C_);

    for (int i = t; i < 256 * 8; i += 256) {
        int rr = i >> 3, v8 = i & 7;
        int s = ((w << 8) + rr + SHIFT_) & (L_ - 1);
        const uint4* krow = (const uint4*)(qkv + base + (size_t)s * (3 * C_) + C_ + h * D_);
        const uint4* vrow = (const uint4*)(qkv + base + (size_t)s * (3 * C_) + 2 * C_ + h * D_);
        float kf[8], vf[8];
        bf8_to_f8(krow[v8], kf);
        bf8_to_f8(vrow[v8], vf);
        *(float4*)(s_k + rr * 64 + v8 * 8)     = *(float4*)kf;
        *(float4*)(s_k + rr * 64 + v8 * 8 + 4) = *(float4*)(kf + 4);
        *(float4*)(s_v + rr * 64 + v8 * 8)     = *(float4*)vf;
        *(float4*)(s_v + rr * 64 + v8 * 8 + 4) = *(float4*)(vf + 4);
    }

    int sq = ((w << 8) + t + SHIFT_) & (L_ - 1);
    const uint4* qrow = (const uint4*)(qkv + base + (size_t)sq * (3 * C_) + h * D_);
    float q[64];
#pragma unroll
    for (int v8 = 0; v8 < 8; v8++) bf8_to_f8(qrow[v8], q + v8 * 8);
    __syncthreads();

    float mx = -1e30f, l = 0.0f;
    float oa[64];
#pragma unroll
    for (int d = 0; d < 64; d++) oa[d] = 0.0f;

    for (int k = 0; k < 256; k++) {
        const float4* kr = (const float4*)(s_k + (k << 6));
        float s = 0.0f;
#pragma unroll
        for (int d4 = 0; d4 < 16; d4++) {
            float4 kv4 = kr[d4];
            s += q[d4 * 4 + 0] * kv4.x + q[d4 * 4 + 1] * kv4.y
               + q[d4 * 4 + 2] * kv4.z + q[d4 * 4 + 3] * kv4.w;
        }
        s *= 0.125f;
        if (s > mx) {
            float cc = __expf(mx - s);
            l *= cc;
#pragma unroll
            for (int d = 0; d < 64; d++) oa[d] *= cc;
            mx = s;
        }
        float p = __expf(s - mx);
        l += p;
        const float4* vr = (const float4*)(s_v + (k << 6));
#pragma unroll
        for (int d4 = 0; d4 < 16; d4++) {
            float4 vv = vr[d4];
            oa[d4 * 4 + 0] += p * vv.x; oa[d4 * 4 + 1] += p * vv.y;
            oa[d4 * 4 + 2] += p * vv.z; oa[d4 * 4 + 3] += p * vv.w;
        }
    }
    float inv = 1.0f / l;
#pragma unroll
    for (int d = 0; d < 64; d++) oa[d] *= inv;
    uint4* orow = (uint4*)(o + ((size_t)b * L_ + sq) * C_ + h * D_);
#pragma unroll
    for (int v8 = 0; v8 < 8; v8++) orow[v8] = f8_to_bf8(oa + v8 * 8);
}

// ---------------------------------------------------------------------------
// Cross-attention (bf16 in/out, fp32 compute)
// ---------------------------------------------------------------------------
__global__ void __launch_bounds__(256, 1) xattn_kernel(
    const bf16* __restrict__ q, const bf16* __restrict__ kv,
    bf16* __restrict__ o)
{
    float* smem = (float*)dsmem;
    float* s_k = smem;
    float* s_v = smem + 256 * 64;
    int h = blockIdx.y, b = blockIdx.z;
    int t = threadIdx.x;

    for (int i = t; i < 256 * 8; i += 256) {
        int rr = i >> 3, v8 = i & 7;
        const uint4* krow = (const uint4*)(kv + ((size_t)b * LCTX + rr) * (2 * C_) + h * D_);
        const uint4* vrow = (const uint4*)(kv + ((size_t)b * LCTX + rr) * (2 * C_) + C_ + h * D_);
        float kf[8], vf[8];
        bf8_to_f8(krow[v8], kf);
        bf8_to_f8(vrow[v8], vf);
        *(float4*)(s_k + rr * 64 + v8 * 8)     = *(float4*)kf;
        *(float4*)(s_k + rr * 64 + v8 * 8 + 4) = *(float4*)(kf + 4);
        *(float4*)(s_v + rr * 64 + v8 * 8)     = *(float4*)vf;
        *(float4*)(s_v + rr * 64 + v8 * 8 + 4) = *(float4*)(vf + 4);
    }

    int pos = blockIdx.x * 256 + t;
    const uint4* qrow = (const uint4*)(q + ((size_t)b * L_ + pos) * C_ + h * D_);
    float qr[64];
#pragma unroll
    for (int v8 = 0; v8 < 8; v8++) bf8_to_f8(qrow[v8], qr + v8 * 8);
    __syncthreads();

    float mx = -1e30f, l = 0.0f;
    float oa[64];
#pragma unroll
    for (int d = 0; d < 64; d++) oa[d] = 0.0f;

    for (int k = 0; k < 256; k++) {
        const float4* kr = (const float4*)(s_k + (k << 6));
        float s = 0.0f;
#pragma unroll
        for (int d4 = 0; d4 < 16; d4++) {
            float4 kv4 = kr[d4];
            s += qr[d4 * 4 + 0] * kv4.x + qr[d4 * 4 + 1] * kv4.y
               + qr[d4 * 4 + 2] * kv4.z + qr[d4 * 4 + 3] * kv4.w;
        }
        s *= 0.125f;
        if (s > mx) {
            float cc = __expf(mx - s);
            l *= cc;
#pragma unroll
            for (int d = 0; d < 64; d++) oa[d] *= cc;
            mx = s;
        }
        float p = __expf(s - mx);
        l += p;
        const float4* vr = (const float4*)(s_v + (k << 6));
#pragma unroll
        for (int d4 = 0; d4 < 16; d4++) {
            float4 vv = vr[d4];
            oa[d4 * 4 + 0] += p * vv.x; oa[d4 * 4 + 1] += p * vv.y;
            oa[d4 * 4 + 2] += p * vv.z; oa[d4 * 4 + 3] += p * vv.w;
        }
    }
    float inv = 1.0f / l;
#pragma unroll
    for (int d = 0; d < 64; d++) oa[d] *= inv;
    uint4* orow = (uint4*)(o + ((size_t)b * L_ + pos) * C_ + h * D_);
#pragma unroll
    for (int v8 = 0; v8 < 8; v8++) orow[v8] = f8_to_bf8(oa + v8 * 8);
}

// ---------------------------------------------------------------------------
// Launch
// ---------------------------------------------------------------------------
extern "C" void kernel_launch(void* const* d_in, const int* in_sizes, int n_in,
                              void* d_out, int out_size)
{
    (void)in_sizes; (void)n_in; (void)out_size;
    const float* x     = (const float*)d_in[0];
    const float* mod   = (const float*)d_in[1];
    const float* ctx   = (const float*)d_in[2];
    const float* mod_w = (const float*)d_in[3];
    const float* mod_b = (const float*)d_in[4];
    const float* n2g   = (const float*)d_in[5];
    const float* n2b   = (const float*)d_in[6];
    const float* qkv_w = (const float*)d_in[7];
    const float* qkv_b = (const float*)d_in[8];
    const float* saow  = (const float*)d_in[9];
    const float* saob  = (const float*)d_in[10];
    const float* q_w   = (const float*)d_in[11];
    const float* q_b   = (const float*)d_in[12];
    const float* kv_w  = (const float*)d_in[13];
    const float* kv_b  = (const float*)d_in[14];
    const float* caow  = (const float*)d_in[15];
    const float* caob  = (const float*)d_in[16];
    const float* w1    = (const float*)d_in[17];
    const float* b1    = (const float*)d_in[18];
    const float* w2    = (const float*)d_in[19];
    const float* b2    = (const float*)d_in[20];
    float* out = (float*)d_out;

    float *sa_, *sh_, *m_, *kv_;
    bf16* wb;
    cudaGetSymbolAddress((void**)&sa_, g_scratch_a);
    cudaGetSymbolAddress((void**)&sh_, g_scratch_h);
    cudaGetSymbolAddress((void**)&m_,  g_mbuf);
    cudaGetSymbolAddress((void**)&kv_, g_kvbuf);
    cudaGetSymbolAddress((void**)&wb,  g_wbuf);

    // bf16 views of scratch
    bf16* qkv_bf    = (bf16*)sa_;                                  // BL x 3072
    bf16* q_bf      = (bf16*)sa_;                                  // BL x 1024 (aliases qkv, disjoint lifetime)
    bf16* hidden_bf = (bf16*)sa_ + (size_t)BL_ * 3 * C_;           // BL x 4096
    bf16* h_bf      = (bf16*)sh_;                                  // BL x 1024
    bf16* kv_bf     = (bf16*)kv_;                                  // B x 256 x 2048

    // converted weights (offsets in elements)
    bf16* qkvW = wb;                       // 1024*3072
    bf16* saW  = qkvW + 1024 * 3072;       // 1024*1024
    bf16* qW   = saW  + 1024 * 1024;       // 1024*1024
    bf16* kvW  = qW   + 1024 * 1024;       // 1024*2048
    bf16* caW  = kvW  + 1024 * 2048;       // 1024*1024
    bf16* w1W  = caW  + 1024 * 1024;       // 1024*4096
    bf16* w2W  = w1W  + 1024 * 4096;       // 4096*1024
    bf16* ctxB = w2W  + 4096 * 1024;       // 4*256*1024

    cudaFuncSetAttribute(wattn_kernel, cudaFuncAttributeMaxDynamicSharedMemorySize, 131072);
    cudaFuncSetAttribute(xattn_kernel, cudaFuncAttributeMaxDynamicSharedMemorySize, 131072);
    cudaFuncSetAttribute(tgemm_kernel<0,1>, cudaFuncAttributeMaxDynamicSharedMemorySize, TG_SMEM);
    cudaFuncSetAttribute(tgemm_kernel<1,1>, cudaFuncAttributeMaxDynamicSharedMemorySize, TG_SMEM);
    cudaFuncSetAttribute(tgemm_kernel<2,0>, cudaFuncAttributeMaxDynamicSharedMemorySize, TG_SMEM);
    cudaFuncSetAttribute(tgemm_kernel<3,0>, cudaFuncAttributeMaxDynamicSharedMemorySize, TG_SMEM);

    // 0. weight + ctx conversion to bf16
    f2b_kernel<<<1024 * 3072 / 1024, 256>>>(qkv_w, qkvW, 1024 * 3072);
    f2b_kernel<<<1024 * 1024 / 1024, 256>>>(saow,  saW,  1024 * 1024);
    f2b_kernel<<<1024 * 1024 / 1024, 256>>>(q_w,   qW,   1024 * 1024);
    f2b_kernel<<<1024 * 2048 / 1024, 256>>>(kv_w,  kvW,  1024 * 2048);
    f2b_kernel<<<1024 * 1024 / 1024, 256>>>(caow,  caW,  1024 * 1024);
    f2b_kernel<<<1024 * 4096 / 1024, 256>>>(w1,    w1W,  1024 * 4096);
    f2b_kernel<<<4096 * 1024 / 1024, 256>>>(w2,    w2W,  4096 * 1024);
    f2b_kernel<<<B_ * LCTX * C_ / 1024, 256>>>(ctx, ctxB, B_ * LCTX * C_);

    // 1. modulation vectors
    mod_gemm_kernel<<<dim3(24, 4), 256>>>(mod, mod_w, mod_b, m_);
    // 2. h = LN(x)*(1+sc_msa) + sh_msa   -> bf16
    ln_kernel<<<BL_, 256>>>(x, h_bf, m_ + C_, m_, SIXC, 1.0f);
    // 3. qkv = h @ qkv_w + b  -> bf16
    tgemm_kernel<0,1><<<dim3(24, 256), 256, TG_SMEM>>>(h_bf, qkvW, qkv_b, nullptr, nullptr,
                                                       qkv_bf, BL_, 3 * C_, C_, 0);
    // 4. windowed self-attention -> bf16
    wattn_kernel<<<dim3(16, 32, 4), 256, 131072>>>(qkv_bf, h_bf);
    // 5. out = x + (o @ sa_out_w + b) * g_msa   (fp32)
    tgemm_kernel<3,0><<<dim3(8, 256), 256, TG_SMEM>>>(h_bf, saW, saob, x, m_ + 2 * C_,
                                                      out, BL_, C_, C_, SIXC);
    // 6. h2 = LN(out)*norm2_g + norm2_b -> bf16
    ln_kernel<<<BL_, 256>>>(out, h_bf, n2g, n2b, 0, 0.0f);
    // 7. q = h2 @ q_w + b -> bf16
    tgemm_kernel<0,1><<<dim3(8, 256), 256, TG_SMEM>>>(h_bf, qW, q_b, nullptr, nullptr,
                                                      q_bf, BL_, C_, C_, 0);
    // 8. kv = ctx @ kv_w + b -> bf16
    tgemm_kernel<0,1><<<dim3(16, 8), 256, TG_SMEM>>>(ctxB, kvW, kv_b, nullptr, nullptr,
                                                     kv_bf, B_ * LCTX, 2 * C_, C_, 0);
    // 9. cross-attention -> bf16
    xattn_kernel<<<dim3(32, 16, 4), 256, 131072>>>(q_bf, kv_bf, h_bf);
    // 10. out += o @ ca_out_w + b  (fp32)
    tgemm_kernel<2,0><<<dim3(8, 256), 256, TG_SMEM>>>(h_bf, caW, caob, out, nullptr,
                                                      out, BL_, C_, C_, 0);
    // 11. h = LN(out)*(1+sc_mlp) + sh_mlp -> bf16
    ln_kernel<<<BL_, 256>>>(out, h_bf, m_ + 4 * C_, m_ + 3 * C_, SIXC, 1.0f);
    // 12. u = gelu(h @ w1 + b1) -> bf16
    tgemm_kernel<1,1><<<dim3(32, 256), 256, TG_SMEM>>>(h_bf, w1W, b1, nullptr, nullptr,
                                                       hidden_bf, BL_, MLP_, C_, 0);
    // 13. out += (u @ w2 + b2) * g_mlp  (fp32)
    tgemm_kernel<3,0><<<dim3(8, 256), 256, TG_SMEM>>>(hidden_bf, w2W, b2, out, m_ + 5 * C_,
                                                      out, BL_, C_, MLP_, SIXC);
}

// round 5
// speedup vs baseline: 5.5430x; 1.4740x over previous
#include <cuda_runtime.h>
#include <cuda_bf16.h>
#include <math.h>
#include <stdint.h>

#define B_     4
#define L_     8192
#define C_     1024
#define H_     16
#define D_     64
#define LCTX   256
#define SHIFT_ 128
#define MLP_   4096
#define BL_    (B_ * L_)   // 32768
#define SIXC   (6 * C_)

typedef __nv_bfloat16 bf16;
typedef __nv_bfloat162 bf162;

// single shared-memory symbol, cast per kernel
extern __shared__ __align__(16) char dsmem[];

// ---------------------------------------------------------------------------
// Scratch (device globals)
// ---------------------------------------------------------------------------
__device__ float g_scratch_a[(size_t)BL_ * MLP_];     // bf16 views: qkv/q + mlp hidden
__device__ float g_scratch_h[(size_t)BL_ * C_];       // bf16 view: LN / attn outputs
__device__ float g_mbuf[B_ * SIXC];                   // modulation vectors (fp32)
__device__ float g_kvbuf[B_ * LCTX * 2 * C_];         // bf16 view: cross-attn K,V
__device__ bf16  g_wbuf[17825792 + 1024];             // converted weights + ctx

// ---------------------------------------------------------------------------
// fp32 -> bf16 conversion
// ---------------------------------------------------------------------------
__global__ void __launch_bounds__(256) f2b_kernel(
    const float* __restrict__ in, bf16* __restrict__ out, int n)
{
    int i = (blockIdx.x * 256 + threadIdx.x) * 4;
    if (i < n) {
        float4 v = *(const float4*)(in + i);
        *(bf162*)(out + i)     = __floats2bfloat162_rn(v.x, v.y);
        *(bf162*)(out + i + 2) = __floats2bfloat162_rn(v.z, v.w);
    }
}

// ---------------------------------------------------------------------------
// Small GEMM: m = silu(mod) @ mod_w + mod_b  (fp32)
// ---------------------------------------------------------------------------
__global__ void __launch_bounds__(256) mod_gemm_kernel(
    const float* __restrict__ mod, const float* __restrict__ W,
    const float* __restrict__ bias, float* __restrict__ out)
{
    int b = blockIdx.y;
    int n = blockIdx.x * 256 + threadIdx.x;
    __shared__ float sa[C_];
    for (int k = threadIdx.x; k < C_; k += 256) {
        float v = mod[b * C_ + k];
        sa[k] = v / (1.0f + expf(-v));
    }
    __syncthreads();
    float acc = bias[n];
#pragma unroll 8
    for (int k = 0; k < C_; k++)
        acc += sa[k] * W[(size_t)k * SIXC + n];
    out[b * SIXC + n] = acc;
}

// ---------------------------------------------------------------------------
// LayerNorm + modulation, bf16 output
// ---------------------------------------------------------------------------
__global__ void __launch_bounds__(256) ln_kernel(
    const float* __restrict__ x, bf16* __restrict__ out,
    const float* __restrict__ scale, const float* __restrict__ shift,
    int bstride, float sadd)
{
    int row = blockIdx.x;
    int b = row >> 13;
    const float4* xr = (const float4*)(x + (size_t)row * C_);
    float4 v = xr[threadIdx.x];
    float s  = v.x + v.y + v.z + v.w;
    float sq = v.x * v.x + v.y * v.y + v.z * v.z + v.w * v.w;
#pragma unroll
    for (int o = 16; o > 0; o >>= 1) {
        s  += __shfl_xor_sync(0xffffffffu, s,  o);
        sq += __shfl_xor_sync(0xffffffffu, sq, o);
    }
    __shared__ float rs[8], rq[8];
    int warp = threadIdx.x >> 5, lane = threadIdx.x & 31;
    if (lane == 0) { rs[warp] = s; rq[warp] = sq; }
    __syncthreads();
    s = 0.0f; sq = 0.0f;
#pragma unroll
    for (int i = 0; i < 8; i++) { s += rs[i]; sq += rq[i]; }
    float mean = s * (1.0f / C_);
    float var  = sq * (1.0f / C_) - mean * mean;
    float rstd = rsqrtf(var + 1e-6f);

    int c = threadIdx.x << 2;
    const float4 g = *(const float4*)(scale + b * bstride + c);
    const float4 t = *(const float4*)(shift + b * bstride + c);
    float ox = (v.x - mean) * rstd * (sadd + g.x) + t.x;
    float oy = (v.y - mean) * rstd * (sadd + g.y) + t.y;
    float oz = (v.z - mean) * rstd * (sadd + g.z) + t.z;
    float ow = (v.w - mean) * rstd * (sadd + g.w) + t.w;
    bf16* op = out + (size_t)row * C_ + c;
    *(bf162*)(op)     = __floats2bfloat162_rn(ox, oy);
    *(bf162*)(op + 2) = __floats2bfloat162_rn(oz, ow);
}

// ---------------------------------------------------------------------------
// MMA / ldmatrix helpers
// ---------------------------------------------------------------------------
__device__ __forceinline__ void mma16816(float* c, const uint32_t* a,
                                         uint32_t b0, uint32_t b1)
{
    asm volatile(
        "mma.sync.aligned.m16n8k16.row.col.f32.bf16.bf16.f32 "
        "{%0,%1,%2,%3}, {%4,%5,%6,%7}, {%8,%9}, {%0,%1,%2,%3};\n"
        : "+f"(c[0]), "+f"(c[1]), "+f"(c[2]), "+f"(c[3])
        : "r"(a[0]), "r"(a[1]), "r"(a[2]), "r"(a[3]), "r"(b0), "r"(b1));
}

__device__ __forceinline__ void ldsm4(uint32_t* r, const bf16* p)
{
    uint32_t a = (uint32_t)__cvta_generic_to_shared(p);
    asm volatile("ldmatrix.sync.aligned.m8n8.x4.shared.b16 {%0,%1,%2,%3}, [%4];\n"
                 : "=r"(r[0]), "=r"(r[1]), "=r"(r[2]), "=r"(r[3]) : "r"(a));
}

__device__ __forceinline__ void ldsm4t(uint32_t* r, const bf16* p)
{
    uint32_t a = (uint32_t)__cvta_generic_to_shared(p);
    asm volatile("ldmatrix.sync.aligned.m8n8.x4.trans.shared.b16 {%0,%1,%2,%3}, [%4];\n"
                 : "=r"(r[0]), "=r"(r[1]), "=r"(r[2]), "=r"(r[3]) : "r"(a));
}

// split fp32 pair into bf16x2 hi + bf16x2 lo (compensated)
__device__ __forceinline__ void split2(float a, float b, uint32_t& hi, uint32_t& lo)
{
    bf162 h = __floats2bfloat162_rn(a, b);
    float2 hf = __bfloat1622float2(h);
    bf162 l = __floats2bfloat162_rn(a - hf.x, b - hf.y);
    hi = *(uint32_t*)&h;
    lo = *(uint32_t*)&l;
}

// ---------------------------------------------------------------------------
// Flash attention (256 q x 256 kv x D=64 per block). 8 warps, 32 q-rows each.
// QK^T bf16 mma (exact: inputs already bf16), fp32 online softmax over 32-key
// chunks, PV with compensated bf16 P (hi+lo). ROLL folds roll(+-128) indexing.
// ---------------------------------------------------------------------------
#define FA_SMEM (3 * 256 * 72 * 2)   // 110592 bytes

template <bool ROLL>
__global__ void __launch_bounds__(256, 1) fattn_kernel(
    const bf16* __restrict__ qp, const bf16* __restrict__ kp,
    const bf16* __restrict__ vp, bf16* __restrict__ op,
    size_t qbatch, int qrs, size_t kbatch, int krs)
{
    bf16* sQ = (bf16*)dsmem;
    bf16* sK = sQ + 256 * 72;
    bf16* sV = sK + 256 * 72;
    int h = blockIdx.x, wt = blockIdx.y, b = blockIdx.z;
    int tid = threadIdx.x, lane = tid & 31, wid = tid >> 5;

    const bf16* qb = qp + (size_t)b * qbatch + h * 64;
    const bf16* kb = kp + (size_t)b * kbatch + h * 64;
    const bf16* vb = vp + (size_t)b * kbatch + h * 64;

    for (int i = tid; i < 2048; i += 256) {
        int r = i >> 3, c = (i & 7) * 8;
        int qr = ROLL ? (((wt << 8) + r + SHIFT_) & (L_ - 1)) : ((wt << 8) + r);
        int kr = ROLL ? qr : r;
        *(uint4*)(sQ + r * 72 + c) = *(const uint4*)(qb + (size_t)qr * qrs + c);
        *(uint4*)(sK + r * 72 + c) = *(const uint4*)(kb + (size_t)kr * krs + c);
        *(uint4*)(sV + r * 72 + c) = *(const uint4*)(vb + (size_t)kr * krs + c);
    }
    __syncthreads();

    // Q fragments: resident for whole kernel. [mtile][k16-group][4 regs]
    int m0 = wid * 32;
    uint32_t qf[2][4][4];
#pragma unroll
    for (int mt = 0; mt < 2; mt++)
#pragma unroll
        for (int dg = 0; dg < 4; dg++)
            ldsm4(qf[mt][dg],
                  sQ + (m0 + mt * 16 + (lane & 15)) * 72 + dg * 16 + (lane >> 4) * 8);

    float o_acc[2][8][4];
#pragma unroll
    for (int mt = 0; mt < 2; mt++)
#pragma unroll
        for (int dt = 0; dt < 8; dt++)
#pragma unroll
            for (int q = 0; q < 4; q++) o_acc[mt][dt][q] = 0.0f;

    float m_run[2][2], l_run[2][2];
#pragma unroll
    for (int mt = 0; mt < 2; mt++) {
        m_run[mt][0] = m_run[mt][1] = -1e30f;
        l_run[mt][0] = l_run[mt][1] = 0.0f;
    }

    for (int kc = 0; kc < 8; kc++) {
        // --- S = Q K^T for 32-key chunk ---
        float s[2][4][4];
#pragma unroll
        for (int mt = 0; mt < 2; mt++)
#pragma unroll
            for (int j = 0; j < 4; j++)
#pragma unroll
                for (int q = 0; q < 4; q++) s[mt][j][q] = 0.0f;

        uint32_t kf[2][4][4];   // [key16-group][d16-group][4]
#pragma unroll
        for (int kg = 0; kg < 2; kg++)
#pragma unroll
            for (int dg = 0; dg < 4; dg++)
                ldsm4(kf[kg][dg],
                      sK + (kc * 32 + kg * 16 + (lane & 15)) * 72 + dg * 16 + (lane >> 4) * 8);

#pragma unroll
        for (int mt = 0; mt < 2; mt++)
#pragma unroll
            for (int j = 0; j < 4; j++) {
                int kg = j >> 1, sel = j & 1;
#pragma unroll
                for (int dg = 0; dg < 4; dg++)
                    mma16816(s[mt][j], qf[mt][dg], kf[kg][dg][sel], kf[kg][dg][sel + 2]);
            }

        // --- scale + online softmax ---
#pragma unroll
        for (int mt = 0; mt < 2; mt++)
#pragma unroll
            for (int j = 0; j < 4; j++)
#pragma unroll
                for (int q = 0; q < 4; q++) s[mt][j][q] *= 0.125f;

#pragma unroll
        for (int mt = 0; mt < 2; mt++) {
#pragma unroll
            for (int half = 0; half < 2; half++) {
                float cm = -1e30f;
#pragma unroll
                for (int j = 0; j < 4; j++) {
                    cm = fmaxf(cm, s[mt][j][half * 2]);
                    cm = fmaxf(cm, s[mt][j][half * 2 + 1]);
                }
                cm = fmaxf(cm, __shfl_xor_sync(0xffffffffu, cm, 1));
                cm = fmaxf(cm, __shfl_xor_sync(0xffffffffu, cm, 2));
                float newm = fmaxf(m_run[mt][half], cm);
                float fac = __expf(m_run[mt][half] - newm);
                m_run[mt][half] = newm;
                l_run[mt][half] *= fac;
#pragma unroll
                for (int dt = 0; dt < 8; dt++) {
                    o_acc[mt][dt][half * 2]     *= fac;
                    o_acc[mt][dt][half * 2 + 1] *= fac;
                }
                float ps = 0.0f;
#pragma unroll
                for (int j = 0; j < 4; j++) {
                    float p0 = __expf(s[mt][j][half * 2]     - newm);
                    float p1 = __expf(s[mt][j][half * 2 + 1] - newm);
                    s[mt][j][half * 2]     = p0;
                    s[mt][j][half * 2 + 1] = p1;
                    ps += p0 + p1;
                }
                l_run[mt][half] += ps;
            }
        }

        // --- pack P into compensated bf16 A-fragments ---
        uint32_t ah[2][2][4], al[2][2][4];  // [mtile][key16-group][4]
#pragma unroll
        for (int mt = 0; mt < 2; mt++)
#pragma unroll
            for (int kg = 0; kg < 2; kg++) {
                split2(s[mt][2 * kg][0],     s[mt][2 * kg][1],     ah[mt][kg][0], al[mt][kg][0]);
                split2(s[mt][2 * kg][2],     s[mt][2 * kg][3],     ah[mt][kg][1], al[mt][kg][1]);
                split2(s[mt][2 * kg + 1][0], s[mt][2 * kg + 1][1], ah[mt][kg][2], al[mt][kg][2]);
                split2(s[mt][2 * kg + 1][2], s[mt][2 * kg + 1][3], ah[mt][kg][3], al[mt][kg][3]);
            }

        // --- O += P V ---
        uint32_t vf[2][4][4];   // [key16-group][d16-group][4]
#pragma unroll
        for (int kg = 0; kg < 2; kg++)
#pragma unroll
            for (int dg = 0; dg < 4; dg++)
                ldsm4t(vf[kg][dg],
                       sV + (kc * 32 + kg * 16 + (lane & 15)) * 72 + dg * 16 + (lane >> 4) * 8);

#pragma unroll
        for (int mt = 0; mt < 2; mt++)
#pragma unroll
            for (int dt = 0; dt < 8; dt++) {
                int dg = dt >> 1, sel = dt & 1;
#pragma unroll
                for (int kg = 0; kg < 2; kg++) {
                    mma16816(o_acc[mt][dt], ah[mt][kg],
                             vf[kg][dg][sel * 2], vf[kg][dg][sel * 2 + 1]);
                    mma16816(o_acc[mt][dt], al[mt][kg],
                             vf[kg][dg][sel * 2], vf[kg][dg][sel * 2 + 1]);
                }
            }
    }

    // --- finalize: 1/l and write (bf16) ---
#pragma unroll
    for (int mt = 0; mt < 2; mt++) {
        float inv[2];
#pragma unroll
        for (int half = 0; half < 2; half++) {
            float l = l_run[mt][half];
            l += __shfl_xor_sync(0xffffffffu, l, 1);
            l += __shfl_xor_sync(0xffffffffu, l, 2);
            inv[half] = 1.0f / l;
        }
        int r0 = m0 + mt * 16 + (lane >> 2);
        int g0 = (wt << 8) + r0;
        int g1 = g0 + 8;
        if (ROLL) {
            g0 = (g0 + SHIFT_) & (L_ - 1);
            g1 = (g1 + SHIFT_) & (L_ - 1);
        }
        bf16* row0 = op + ((size_t)b * L_ + g0) * C_ + h * 64 + 2 * (lane & 3);
        bf16* row1 = op + ((size_t)b * L_ + g1) * C_ + h * 64 + 2 * (lane & 3);
#pragma unroll
        for (int dt = 0; dt < 8; dt++) {
            *(bf162*)(row0 + dt * 8) =
                __floats2bfloat162_rn(o_acc[mt][dt][0] * inv[0], o_acc[mt][dt][1] * inv[0]);
            *(bf162*)(row1 + dt * 8) =
                __floats2bfloat162_rn(o_acc[mt][dt][2] * inv[1], o_acc[mt][dt][3] * inv[1]);
        }
    }
}

// ---------------------------------------------------------------------------
// bf16 tensor-core GEMM (unchanged from round 4)
// ---------------------------------------------------------------------------
__device__ __forceinline__ float gelu_tanh(float v)
{
    float v3 = v * v * v;
    float t = tanhf(0.7978845608028654f * (v + 0.044715f * v3));
    return 0.5f * v * (1.0f + t);
}

__device__ __forceinline__ void cpasync16(bf16* s, const bf16* g)
{
    uint32_t sa = (uint32_t)__cvta_generic_to_shared(s);
    asm volatile("cp.async.cg.shared.global [%0], [%1], 16;\n" :: "r"(sa), "l"(g));
}

#define BK     32
#define APAD   40
#define BPAD   136
#define ASZ    (128 * APAD)
#define BSZ    (BK * BPAD)
#define STG    (ASZ + BSZ)
#define NSTAGE 3
#define TG_SMEM (NSTAGE * STG * 2)

template <int MODE, int OUTB>
__global__ void __launch_bounds__(256) tgemm_kernel(
    const bf16* __restrict__ A, const bf16* __restrict__ Bw,
    const float* __restrict__ bias, const float* __restrict__ resid,
    const float* __restrict__ gate, void* __restrict__ Cout,
    int M, int N, int K, int gstride)
{
    bf16* smem = (bf16*)dsmem;

    int tid = threadIdx.x;
    int bm = blockIdx.y * 128;
    int bn = blockIdx.x * 128;
    int lane = tid & 31;
    int wid  = tid >> 5;
    int wm = (wid & 1) * 64;
    int wn = (wid >> 1) * 32;

    int arow = tid >> 1;
    int acol = (tid & 1) * 16;
    int brow = tid >> 3;
    int bcol = (tid & 7) * 16;
    const bf16* Ag = A + (size_t)(bm + arow) * K + acol;
    const bf16* Bg = Bw + (size_t)brow * N + bn + bcol;

    float acc[4][4][4];
#pragma unroll
    for (int mi = 0; mi < 4; mi++)
#pragma unroll
        for (int ni = 0; ni < 4; ni++)
#pragma unroll
            for (int q = 0; q < 4; q++) acc[mi][ni][q] = 0.0f;

    int nk = K / BK;
#pragma unroll
    for (int s = 0; s < NSTAGE - 1; s++) {
        bf16* As = smem + s * STG;
        bf16* Bs = As + ASZ;
        int k0 = s * BK;
        cpasync16(As + arow * APAD + acol,     Ag + k0);
        cpasync16(As + arow * APAD + acol + 8, Ag + k0 + 8);
        cpasync16(Bs + brow * BPAD + bcol,     Bg + (size_t)k0 * N);
        cpasync16(Bs + brow * BPAD + bcol + 8, Bg + (size_t)k0 * N + 8);
        asm volatile("cp.async.commit_group;\n" ::);
    }

    for (int kt = 0; kt < nk; kt++) {
        int ldst = kt + NSTAGE - 1;
        if (ldst < nk) {
            bf16* As = smem + (ldst % NSTAGE) * STG;
            bf16* Bs = As + ASZ;
            int k0 = ldst * BK;
            cpasync16(As + arow * APAD + acol,     Ag + k0);
            cpasync16(As + arow * APAD + acol + 8, Ag + k0 + 8);
            cpasync16(Bs + brow * BPAD + bcol,     Bg + (size_t)k0 * N);
            cpasync16(Bs + brow * BPAD + bcol + 8, Bg + (size_t)k0 * N + 8);
        }
        asm volatile("cp.async.commit_group;\n" ::);
        asm volatile("cp.async.wait_group %0;\n" :: "n"(NSTAGE - 1));
        __syncthreads();

        const bf16* As = smem + (kt % NSTAGE) * STG;
        const bf16* Bs = As + ASZ;

#pragma unroll
        for (int ks = 0; ks < 2; ks++) {
            uint32_t af[4][4], bfr[2][4];
#pragma unroll
            for (int mi = 0; mi < 4; mi++)
                ldsm4(af[mi], As + (wm + mi * 16 + (lane & 15)) * APAD + ks * 16 + (lane >> 4) * 8);
#pragma unroll
            for (int nh = 0; nh < 2; nh++)
                ldsm4t(bfr[nh], Bs + (ks * 16 + (lane & 15)) * BPAD + wn + nh * 16 + (lane >> 4) * 8);
#pragma unroll
            for (int mi = 0; mi < 4; mi++)
#pragma unroll
                for (int ni = 0; ni < 4; ni++)
                    mma16816(acc[mi][ni], af[mi],
                             bfr[ni >> 1][(ni & 1) * 2], bfr[ni >> 1][(ni & 1) * 2 + 1]);
        }
        __syncthreads();
    }

    int r = lane >> 2, c = lane & 3;
#pragma unroll
    for (int mi = 0; mi < 4; mi++) {
#pragma unroll
        for (int r2 = 0; r2 < 2; r2++) {
            int row = bm + wm + mi * 16 + r + r2 * 8;
            int bofs = (row >> 13) * gstride;
#pragma unroll
            for (int ni = 0; ni < 4; ni++) {
                int col = bn + wn + ni * 8 + 2 * c;
                float2 bi = *(const float2*)(bias + col);
                float vx = acc[mi][ni][r2 * 2 + 0] + bi.x;
                float vy = acc[mi][ni][r2 * 2 + 1] + bi.y;
                if (MODE == 1) { vx = gelu_tanh(vx); vy = gelu_tanh(vy); }
                if (MODE == 2) {
                    float2 rr = *(const float2*)(resid + (size_t)row * N + col);
                    vx += rr.x; vy += rr.y;
                }
                if (MODE == 3) {
                    float2 rr = *(const float2*)(resid + (size_t)row * N + col);
                    float2 gg = *(const float2*)(gate + bofs + col);
                    vx = rr.x + vx * gg.x;
                    vy = rr.y + vy * gg.y;
                }
                if (OUTB) {
                    *(bf162*)((bf16*)Cout + (size_t)row * N + col) =
                        __floats2bfloat162_rn(vx, vy);
                } else {
                    float2 v; v.x = vx; v.y = vy;
                    *(float2*)((float*)Cout + (size_t)row * N + col) = v;
                }
            }
        }
    }
}

// ---------------------------------------------------------------------------
// Launch
// ---------------------------------------------------------------------------
extern "C" void kernel_launch(void* const* d_in, const int* in_sizes, int n_in,
                              void* d_out, int out_size)
{
    (void)in_sizes; (void)n_in; (void)out_size;
    const float* x     = (const float*)d_in[0];
    const float* mod   = (const float*)d_in[1];
    const float* ctx   = (const float*)d_in[2];
    const float* mod_w = (const float*)d_in[3];
    const float* mod_b = (const float*)d_in[4];
    const float* n2g   = (const float*)d_in[5];
    const float* n2b   = (const float*)d_in[6];
    const float* qkv_w = (const float*)d_in[7];
    const float* qkv_b = (const float*)d_in[8];
    const float* saow  = (const float*)d_in[9];
    const float* saob  = (const float*)d_in[10];
    const float* q_w   = (const float*)d_in[11];
    const float* q_b   = (const float*)d_in[12];
    const float* kv_w  = (const float*)d_in[13];
    const float* kv_b  = (const float*)d_in[14];
    const float* caow  = (const float*)d_in[15];
    const float* caob  = (const float*)d_in[16];
    const float* w1    = (const float*)d_in[17];
    const float* b1    = (const float*)d_in[18];
    const float* w2    = (const float*)d_in[19];
    const float* b2    = (const float*)d_in[20];
    float* out = (float*)d_out;

    float *sa_, *sh_, *m_, *kv_;
    bf16* wb;
    cudaGetSymbolAddress((void**)&sa_, g_scratch_a);
    cudaGetSymbolAddress((void**)&sh_, g_scratch_h);
    cudaGetSymbolAddress((void**)&m_,  g_mbuf);
    cudaGetSymbolAddress((void**)&kv_, g_kvbuf);
    cudaGetSymbolAddress((void**)&wb,  g_wbuf);

    bf16* qkv_bf    = (bf16*)sa_;                          // BL x 3072
    bf16* q_bf      = (bf16*)sa_;                          // BL x 1024 (aliases qkv)
    bf16* hidden_bf = (bf16*)sa_ + (size_t)BL_ * 3 * C_;   // BL x 4096
    bf16* h_bf      = (bf16*)sh_;                          // BL x 1024
    bf16* kv_bf     = (bf16*)kv_;                          // B x 256 x 2048

    bf16* qkvW = wb;
    bf16* saW  = qkvW + 1024 * 3072;
    bf16* qW   = saW  + 1024 * 1024;
    bf16* kvW  = qW   + 1024 * 1024;
    bf16* caW  = kvW  + 1024 * 2048;
    bf16* w1W  = caW  + 1024 * 1024;
    bf16* w2W  = w1W  + 1024 * 4096;
    bf16* ctxB = w2W  + 4096 * 1024;

    cudaFuncSetAttribute(fattn_kernel<true>,  cudaFuncAttributeMaxDynamicSharedMemorySize, FA_SMEM);
    cudaFuncSetAttribute(fattn_kernel<false>, cudaFuncAttributeMaxDynamicSharedMemorySize, FA_SMEM);
    cudaFuncSetAttribute(tgemm_kernel<0,1>, cudaFuncAttributeMaxDynamicSharedMemorySize, TG_SMEM);
    cudaFuncSetAttribute(tgemm_kernel<1,1>, cudaFuncAttributeMaxDynamicSharedMemorySize, TG_SMEM);
    cudaFuncSetAttribute(tgemm_kernel<2,0>, cudaFuncAttributeMaxDynamicSharedMemorySize, TG_SMEM);
    cudaFuncSetAttribute(tgemm_kernel<3,0>, cudaFuncAttributeMaxDynamicSharedMemorySize, TG_SMEM);

    // 0. weight + ctx conversion to bf16
    f2b_kernel<<<1024 * 3072 / 1024, 256>>>(qkv_w, qkvW, 1024 * 3072);
    f2b_kernel<<<1024 * 1024 / 1024, 256>>>(saow,  saW,  1024 * 1024);
    f2b_kernel<<<1024 * 1024 / 1024, 256>>>(q_w,   qW,   1024 * 1024);
    f2b_kernel<<<1024 * 2048 / 1024, 256>>>(kv_w,  kvW,  1024 * 2048);
    f2b_kernel<<<1024 * 1024 / 1024, 256>>>(caow,  caW,  1024 * 1024);
    f2b_kernel<<<1024 * 4096 / 1024, 256>>>(w1,    w1W,  1024 * 4096);
    f2b_kernel<<<4096 * 1024 / 1024, 256>>>(w2,    w2W,  4096 * 1024);
    f2b_kernel<<<B_ * LCTX * C_ / 1024, 256>>>(ctx, ctxB, B_ * LCTX * C_);

    // 1. modulation vectors
    mod_gemm_kernel<<<dim3(24, 4), 256>>>(mod, mod_w, mod_b, m_);
    // 2. h = LN(x)*(1+sc_msa) + sh_msa   -> bf16
    ln_kernel<<<BL_, 256>>>(x, h_bf, m_ + C_, m_, SIXC, 1.0f);
    // 3. qkv = h @ qkv_w + b  -> bf16
    tgemm_kernel<0,1><<<dim3(24, 256), 256, TG_SMEM>>>(h_bf, qkvW, qkv_b, nullptr, nullptr,
                                                       qkv_bf, BL_, 3 * C_, C_, 0);
    // 4. windowed self-attention (MMA flash, rolls folded) -> bf16
    fattn_kernel<true><<<dim3(16, 32, 4), 256, FA_SMEM>>>(
        qkv_bf, qkv_bf + C_, qkv_bf + 2 * C_, h_bf,
        (size_t)L_ * 3 * C_, 3 * C_, (size_t)L_ * 3 * C_, 3 * C_);
    // 5. out = x + (o @ sa_out_w + b) * g_msa   (fp32)
    tgemm_kernel<3,0><<<dim3(8, 256), 256, TG_SMEM>>>(h_bf, saW, saob, x, m_ + 2 * C_,
                                                      out, BL_, C_, C_, SIXC);
    // 6. h2 = LN(out)*norm2_g + norm2_b -> bf16
    ln_kernel<<<BL_, 256>>>(out, h_bf, n2g, n2b, 0, 0.0f);
    // 7. q = h2 @ q_w + b -> bf16
    tgemm_kernel<0,1><<<dim3(8, 256), 256, TG_SMEM>>>(h_bf, qW, q_b, nullptr, nullptr,
                                                      q_bf, BL_, C_, C_, 0);
    // 8. kv = ctx @ kv_w + b -> bf16
    tgemm_kernel<0,1><<<dim3(16, 8), 256, TG_SMEM>>>(ctxB, kvW, kv_b, nullptr, nullptr,
                                                     kv_bf, B_ * LCTX, 2 * C_, C_, 0);
    // 9. cross-attention (MMA flash) -> bf16
    fattn_kernel<false><<<dim3(16, 32, 4), 256, FA_SMEM>>>(
        q_bf, kv_bf, kv_bf + C_, h_bf,
        (size_t)L_ * C_, C_, (size_t)LCTX * 2 * C_, 2 * C_);
    // 10. out += o @ ca_out_w + b  (fp32)
    tgemm_kernel<2,0><<<dim3(8, 256), 256, TG_SMEM>>>(h_bf, caW, caob, out, nullptr,
                                                      out, BL_, C_, C_, 0);
    // 11. h = LN(out)*(1+sc_mlp) + sh_mlp -> bf16
    ln_kernel<<<BL_, 256>>>(out, h_bf, m_ + 4 * C_, m_ + 3 * C_, SIXC, 1.0f);
    // 12. u = gelu(h @ w1 + b1) -> bf16
    tgemm_kernel<1,1><<<dim3(32, 256), 256, TG_SMEM>>>(h_bf, w1W, b1, nullptr, nullptr,
                                                       hidden_bf, BL_, MLP_, C_, 0);
    // 13. out += (u @ w2 + b2) * g_mlp  (fp32)
    tgemm_kernel<3,0><<<dim3(8, 256), 256, TG_SMEM>>>(hidden_bf, w2W, b2, out, m_ + 5 * C_,
                                                      out, BL_, C_, MLP_, SIXC);
}

// round 6
// speedup vs baseline: 5.6948x; 1.0274x over previous
#include <cuda_runtime.h>
#include <cuda_bf16.h>
#include <math.h>
#include <stdint.h>

#define B_     4
#define L_     8192
#define C_     1024
#define H_     16
#define D_     64
#define LCTX   256
#define SHIFT_ 128
#define MLP_   4096
#define BL_    (B_ * L_)   // 32768
#define SIXC   (6 * C_)

typedef __nv_bfloat16 bf16;
typedef __nv_bfloat162 bf162;

// single shared-memory symbol, cast per kernel
extern __shared__ __align__(16) char dsmem[];

// ---------------------------------------------------------------------------
// Scratch (device globals)
// ---------------------------------------------------------------------------
__device__ float g_scratch_a[(size_t)BL_ * MLP_];     // bf16 views: qkv/q + mlp hidden
__device__ float g_scratch_h[(size_t)BL_ * C_];       // bf16 view: LN / attn outputs
__device__ float g_mbuf[B_ * SIXC];                   // modulation vectors (fp32)
__device__ float g_kvbuf[B_ * LCTX * 2 * C_];         // bf16 view: cross-attn K,V
__device__ bf16  g_wbuf[17825792 + 1024];             // converted weights + ctx

// ---------------------------------------------------------------------------
// fp32 -> bf16 conversion
// ---------------------------------------------------------------------------
__global__ void __launch_bounds__(256) f2b_kernel(
    const float* __restrict__ in, bf16* __restrict__ out, int n)
{
    int i = (blockIdx.x * 256 + threadIdx.x) * 4;
    if (i < n) {
        float4 v = *(const float4*)(in + i);
        *(bf162*)(out + i)     = __floats2bfloat162_rn(v.x, v.y);
        *(bf162*)(out + i + 2) = __floats2bfloat162_rn(v.z, v.w);
    }
}

// ---------------------------------------------------------------------------
// Small GEMM: m = silu(mod) @ mod_w + mod_b  (fp32)
// ---------------------------------------------------------------------------
__global__ void __launch_bounds__(256) mod_gemm_kernel(
    const float* __restrict__ mod, const float* __restrict__ W,
    const float* __restrict__ bias, float* __restrict__ out)
{
    int b = blockIdx.y;
    int n = blockIdx.x * 256 + threadIdx.x;
    __shared__ float sa[C_];
    for (int k = threadIdx.x; k < C_; k += 256) {
        float v = mod[b * C_ + k];
        sa[k] = v / (1.0f + expf(-v));
    }
    __syncthreads();
    float acc = bias[n];
#pragma unroll 8
    for (int k = 0; k < C_; k++)
        acc += sa[k] * W[(size_t)k * SIXC + n];
    out[b * SIXC + n] = acc;
}

// ---------------------------------------------------------------------------
// LayerNorm + modulation, bf16 output
// ---------------------------------------------------------------------------
__global__ void __launch_bounds__(256) ln_kernel(
    const float* __restrict__ x, bf16* __restrict__ out,
    const float* __restrict__ scale, const float* __restrict__ shift,
    int bstride, float sadd)
{
    int row = blockIdx.x;
    int b = row >> 13;
    const float4* xr = (const float4*)(x + (size_t)row * C_);
    float4 v = xr[threadIdx.x];
    float s  = v.x + v.y + v.z + v.w;
    float sq = v.x * v.x + v.y * v.y + v.z * v.z + v.w * v.w;
#pragma unroll
    for (int o = 16; o > 0; o >>= 1) {
        s  += __shfl_xor_sync(0xffffffffu, s,  o);
        sq += __shfl_xor_sync(0xffffffffu, sq, o);
    }
    __shared__ float rs[8], rq[8];
    int warp = threadIdx.x >> 5, lane = threadIdx.x & 31;
    if (lane == 0) { rs[warp] = s; rq[warp] = sq; }
    __syncthreads();
    s = 0.0f; sq = 0.0f;
#pragma unroll
    for (int i = 0; i < 8; i++) { s += rs[i]; sq += rq[i]; }
    float mean = s * (1.0f / C_);
    float var  = sq * (1.0f / C_) - mean * mean;
    float rstd = rsqrtf(var + 1e-6f);

    int c = threadIdx.x << 2;
    const float4 g = *(const float4*)(scale + b * bstride + c);
    const float4 t = *(const float4*)(shift + b * bstride + c);
    float ox = (v.x - mean) * rstd * (sadd + g.x) + t.x;
    float oy = (v.y - mean) * rstd * (sadd + g.y) + t.y;
    float oz = (v.z - mean) * rstd * (sadd + g.z) + t.z;
    float ow = (v.w - mean) * rstd * (sadd + g.w) + t.w;
    bf16* op = out + (size_t)row * C_ + c;
    *(bf162*)(op)     = __floats2bfloat162_rn(ox, oy);
    *(bf162*)(op + 2) = __floats2bfloat162_rn(oz, ow);
}

// ---------------------------------------------------------------------------
// MMA / ldmatrix helpers
// ---------------------------------------------------------------------------
__device__ __forceinline__ void mma16816(float* c, const uint32_t* a,
                                         uint32_t b0, uint32_t b1)
{
    asm volatile(
        "mma.sync.aligned.m16n8k16.row.col.f32.bf16.bf16.f32 "
        "{%0,%1,%2,%3}, {%4,%5,%6,%7}, {%8,%9}, {%0,%1,%2,%3};\n"
        : "+f"(c[0]), "+f"(c[1]), "+f"(c[2]), "+f"(c[3])
        : "r"(a[0]), "r"(a[1]), "r"(a[2]), "r"(a[3]), "r"(b0), "r"(b1));
}

__device__ __forceinline__ void ldsm4(uint32_t* r, const bf16* p)
{
    uint32_t a = (uint32_t)__cvta_generic_to_shared(p);
    asm volatile("ldmatrix.sync.aligned.m8n8.x4.shared.b16 {%0,%1,%2,%3}, [%4];\n"
                 : "=r"(r[0]), "=r"(r[1]), "=r"(r[2]), "=r"(r[3]) : "r"(a));
}

__device__ __forceinline__ void ldsm4t(uint32_t* r, const bf16* p)
{
    uint32_t a = (uint32_t)__cvta_generic_to_shared(p);
    asm volatile("ldmatrix.sync.aligned.m8n8.x4.trans.shared.b16 {%0,%1,%2,%3}, [%4];\n"
                 : "=r"(r[0]), "=r"(r[1]), "=r"(r[2]), "=r"(r[3]) : "r"(a));
}

// split fp32 pair into bf16x2 hi + bf16x2 lo (compensated)
__device__ __forceinline__ void split2(float a, float b, uint32_t& hi, uint32_t& lo)
{
    bf162 h = __floats2bfloat162_rn(a, b);
    float2 hf = __bfloat1622float2(h);
    bf162 l = __floats2bfloat162_rn(a - hf.x, b - hf.y);
    hi = *(uint32_t*)&h;
    lo = *(uint32_t*)&l;
}

// ---------------------------------------------------------------------------
// Flash attention (256 q x 256 kv x D=64 per block). 8 warps, 32 q-rows each.
// ---------------------------------------------------------------------------
#define FA_SMEM (3 * 256 * 72 * 2)   // 110592 bytes

template <bool ROLL>
__global__ void __launch_bounds__(256, 1) fattn_kernel(
    const bf16* __restrict__ qp, const bf16* __restrict__ kp,
    const bf16* __restrict__ vp, bf16* __restrict__ op,
    size_t qbatch, int qrs, size_t kbatch, int krs)
{
    bf16* sQ = (bf16*)dsmem;
    bf16* sK = sQ + 256 * 72;
    bf16* sV = sK + 256 * 72;
    int h = blockIdx.x, wt = blockIdx.y, b = blockIdx.z;
    int tid = threadIdx.x, lane = tid & 31, wid = tid >> 5;

    const bf16* qb = qp + (size_t)b * qbatch + h * 64;
    const bf16* kb = kp + (size_t)b * kbatch + h * 64;
    const bf16* vb = vp + (size_t)b * kbatch + h * 64;

    for (int i = tid; i < 2048; i += 256) {
        int r = i >> 3, c = (i & 7) * 8;
        int qr = ROLL ? (((wt << 8) + r + SHIFT_) & (L_ - 1)) : ((wt << 8) + r);
        int kr = ROLL ? qr : r;
        *(uint4*)(sQ + r * 72 + c) = *(const uint4*)(qb + (size_t)qr * qrs + c);
        *(uint4*)(sK + r * 72 + c) = *(const uint4*)(kb + (size_t)kr * krs + c);
        *(uint4*)(sV + r * 72 + c) = *(const uint4*)(vb + (size_t)kr * krs + c);
    }
    __syncthreads();

    int m0 = wid * 32;
    uint32_t qf[2][4][4];
#pragma unroll
    for (int mt = 0; mt < 2; mt++)
#pragma unroll
        for (int dg = 0; dg < 4; dg++)
            ldsm4(qf[mt][dg],
                  sQ + (m0 + mt * 16 + (lane & 15)) * 72 + dg * 16 + (lane >> 4) * 8);

    float o_acc[2][8][4];
#pragma unroll
    for (int mt = 0; mt < 2; mt++)
#pragma unroll
        for (int dt = 0; dt < 8; dt++)
#pragma unroll
            for (int q = 0; q < 4; q++) o_acc[mt][dt][q] = 0.0f;

    float m_run[2][2], l_run[2][2];
#pragma unroll
    for (int mt = 0; mt < 2; mt++) {
        m_run[mt][0] = m_run[mt][1] = -1e30f;
        l_run[mt][0] = l_run[mt][1] = 0.0f;
    }

    for (int kc = 0; kc < 8; kc++) {
        float s[2][4][4];
#pragma unroll
        for (int mt = 0; mt < 2; mt++)
#pragma unroll
            for (int j = 0; j < 4; j++)
#pragma unroll
                for (int q = 0; q < 4; q++) s[mt][j][q] = 0.0f;

        uint32_t kf[2][4][4];
#pragma unroll
        for (int kg = 0; kg < 2; kg++)
#pragma unroll
            for (int dg = 0; dg < 4; dg++)
                ldsm4(kf[kg][dg],
                      sK + (kc * 32 + kg * 16 + (lane & 15)) * 72 + dg * 16 + (lane >> 4) * 8);

#pragma unroll
        for (int mt = 0; mt < 2; mt++)
#pragma unroll
            for (int j = 0; j < 4; j++) {
                int kg = j >> 1, sel = j & 1;
#pragma unroll
                for (int dg = 0; dg < 4; dg++)
                    mma16816(s[mt][j], qf[mt][dg], kf[kg][dg][sel], kf[kg][dg][sel + 2]);
            }

#pragma unroll
        for (int mt = 0; mt < 2; mt++)
#pragma unroll
            for (int j = 0; j < 4; j++)
#pragma unroll
                for (int q = 0; q < 4; q++) s[mt][j][q] *= 0.125f;

#pragma unroll
        for (int mt = 0; mt < 2; mt++) {
#pragma unroll
            for (int half = 0; half < 2; half++) {
                float cm = -1e30f;
#pragma unroll
                for (int j = 0; j < 4; j++) {
                    cm = fmaxf(cm, s[mt][j][half * 2]);
                    cm = fmaxf(cm, s[mt][j][half * 2 + 1]);
                }
                cm = fmaxf(cm, __shfl_xor_sync(0xffffffffu, cm, 1));
                cm = fmaxf(cm, __shfl_xor_sync(0xffffffffu, cm, 2));
                float newm = fmaxf(m_run[mt][half], cm);
                float fac = __expf(m_run[mt][half] - newm);
                m_run[mt][half] = newm;
                l_run[mt][half] *= fac;
#pragma unroll
                for (int dt = 0; dt < 8; dt++) {
                    o_acc[mt][dt][half * 2]     *= fac;
                    o_acc[mt][dt][half * 2 + 1] *= fac;
                }
                float ps = 0.0f;
#pragma unroll
                for (int j = 0; j < 4; j++) {
                    float p0 = __expf(s[mt][j][half * 2]     - newm);
                    float p1 = __expf(s[mt][j][half * 2 + 1] - newm);
                    s[mt][j][half * 2]     = p0;
                    s[mt][j][half * 2 + 1] = p1;
                    ps += p0 + p1;
                }
                l_run[mt][half] += ps;
            }
        }

        uint32_t ah[2][2][4], al[2][2][4];
#pragma unroll
        for (int mt = 0; mt < 2; mt++)
#pragma unroll
            for (int kg = 0; kg < 2; kg++) {
                split2(s[mt][2 * kg][0],     s[mt][2 * kg][1],     ah[mt][kg][0], al[mt][kg][0]);
                split2(s[mt][2 * kg][2],     s[mt][2 * kg][3],     ah[mt][kg][1], al[mt][kg][1]);
                split2(s[mt][2 * kg + 1][0], s[mt][2 * kg + 1][1], ah[mt][kg][2], al[mt][kg][2]);
                split2(s[mt][2 * kg + 1][2], s[mt][2 * kg + 1][3], ah[mt][kg][3], al[mt][kg][3]);
            }

        uint32_t vf[2][4][4];
#pragma unroll
        for (int kg = 0; kg < 2; kg++)
#pragma unroll
            for (int dg = 0; dg < 4; dg++)
                ldsm4t(vf[kg][dg],
                       sV + (kc * 32 + kg * 16 + (lane & 15)) * 72 + dg * 16 + (lane >> 4) * 8);

#pragma unroll
        for (int mt = 0; mt < 2; mt++)
#pragma unroll
            for (int dt = 0; dt < 8; dt++) {
                int dg = dt >> 1, sel = dt & 1;
#pragma unroll
                for (int kg = 0; kg < 2; kg++) {
                    mma16816(o_acc[mt][dt], ah[mt][kg],
                             vf[kg][dg][sel * 2], vf[kg][dg][sel * 2 + 1]);
                    mma16816(o_acc[mt][dt], al[mt][kg],
                             vf[kg][dg][sel * 2], vf[kg][dg][sel * 2 + 1]);
                }
            }
    }

#pragma unroll
    for (int mt = 0; mt < 2; mt++) {
        float inv[2];
#pragma unroll
        for (int half = 0; half < 2; half++) {
            float l = l_run[mt][half];
            l += __shfl_xor_sync(0xffffffffu, l, 1);
            l += __shfl_xor_sync(0xffffffffu, l, 2);
            inv[half] = 1.0f / l;
        }
        int r0 = m0 + mt * 16 + (lane >> 2);
        int g0 = (wt << 8) + r0;
        int g1 = g0 + 8;
        if (ROLL) {
            g0 = (g0 + SHIFT_) & (L_ - 1);
            g1 = (g1 + SHIFT_) & (L_ - 1);
        }
        bf16* row0 = op + ((size_t)b * L_ + g0) * C_ + h * 64 + 2 * (lane & 3);
        bf16* row1 = op + ((size_t)b * L_ + g1) * C_ + h * 64 + 2 * (lane & 3);
#pragma unroll
        for (int dt = 0; dt < 8; dt++) {
            *(bf162*)(row0 + dt * 8) =
                __floats2bfloat162_rn(o_acc[mt][dt][0] * inv[0], o_acc[mt][dt][1] * inv[0]);
            *(bf162*)(row1 + dt * 8) =
                __floats2bfloat162_rn(o_acc[mt][dt][2] * inv[1], o_acc[mt][dt][3] * inv[1]);
        }
    }
}

// ---------------------------------------------------------------------------
// bf16 tensor-core GEMM: C = epilogue(A[MxK] @ B[KxN] + bias)
// 128x256 block tile, BK=32, 8 warps (2x4), warp tile 64x64, m16n8k16.bf16,
// 3-stage cp.async, SINGLE __syncthreads per k-tile.
// MODE 0:+bias  1:gelu(+bias)  2:resid+  3:resid+*gate ; OUTB: bf16 output
// Requires M%128==0, N%256==0, K%32==0.
// ---------------------------------------------------------------------------
__device__ __forceinline__ float gelu_tanh(float v)
{
    float v3 = v * v * v;
    float t = tanhf(0.7978845608028654f * (v + 0.044715f * v3));
    return 0.5f * v * (1.0f + t);
}

__device__ __forceinline__ void cpasync16(bf16* s, const bf16* g)
{
    uint32_t sa = (uint32_t)__cvta_generic_to_shared(s);
    asm volatile("cp.async.cg.shared.global [%0], [%1], 16;\n" :: "r"(sa), "l"(g));
}

#define BK     32
#define APAD   40
#define BPAD   264
#define ASZ    (128 * APAD)     // 5120
#define BSZ    (BK * BPAD)      // 8448
#define STG    (ASZ + BSZ)      // 13568 elems
#define NSTAGE 3
#define TG_SMEM (NSTAGE * STG * 2)   // 81408 bytes

template <int MODE, int OUTB>
__global__ void __launch_bounds__(256, 1) tgemm_kernel(
    const bf16* __restrict__ A, const bf16* __restrict__ Bw,
    const float* __restrict__ bias, const float* __restrict__ resid,
    const float* __restrict__ gate, void* __restrict__ Cout,
    int M, int N, int K, int gstride)
{
    bf16* smem = (bf16*)dsmem;

    int tid = threadIdx.x;
    int bm = blockIdx.y * 128;
    int bn = blockIdx.x * 256;
    int lane = tid & 31;
    int wid  = tid >> 5;
    int wm = (wid & 1) * 64;
    int wn = (wid >> 1) * 64;

    // cp.async mapping: A 128x32 (2 chunks/thread), B 32x256 (4 chunks/thread)
    int arow = tid >> 1;
    int acol = (tid & 1) * 16;
    int brow = tid >> 3;
    int bcol = (tid & 7) * 8;
    const bf16* Ag = A + (size_t)(bm + arow) * K + acol;
    const bf16* Bg = Bw + (size_t)brow * N + bn + bcol;

    float acc[4][8][4];
#pragma unroll
    for (int mi = 0; mi < 4; mi++)
#pragma unroll
        for (int ni = 0; ni < 8; ni++)
#pragma unroll
            for (int q = 0; q < 4; q++) acc[mi][ni][q] = 0.0f;

    int nk = K / BK;
    // prologue: stages 0..NSTAGE-2
#pragma unroll
    for (int s = 0; s < NSTAGE - 1; s++) {
        bf16* As = smem + s * STG;
        bf16* Bs = As + ASZ;
        int k0 = s * BK;
        cpasync16(As + arow * APAD + acol,     Ag + k0);
        cpasync16(As + arow * APAD + acol + 8, Ag + k0 + 8);
#pragma unroll
        for (int j = 0; j < 4; j++)
            cpasync16(Bs + brow * BPAD + bcol + j * 64, Bg + (size_t)k0 * N + j * 64);
        asm volatile("cp.async.commit_group;\n" ::);
    }

    for (int kt = 0; kt < nk; kt++) {
        // stage kt must be ready: committed groups 0..kt+NSTAGE-2, allow NSTAGE-2 pending
        asm volatile("cp.async.wait_group %0;\n" :: "n"(NSTAGE - 2));
        __syncthreads();

        // issue loads for stage kt+NSTAGE-1 (safe: its buffer was consumed in iter kt-1)
        int ldst = kt + NSTAGE - 1;
        if (ldst < nk) {
            bf16* As = smem + (ldst % NSTAGE) * STG;
            bf16* Bs = As + ASZ;
            int k0 = ldst * BK;
            cpasync16(As + arow * APAD + acol,     Ag + k0);
            cpasync16(As + arow * APAD + acol + 8, Ag + k0 + 8);
#pragma unroll
            for (int j = 0; j < 4; j++)
                cpasync16(Bs + brow * BPAD + bcol + j * 64, Bg + (size_t)k0 * N + j * 64);
        }
        asm volatile("cp.async.commit_group;\n" ::);

        const bf16* As = smem + (kt % NSTAGE) * STG;
        const bf16* Bs = As + ASZ;

#pragma unroll
        for (int ks = 0; ks < 2; ks++) {
            uint32_t af[4][4], bfr[4][4];
#pragma unroll
            for (int mi = 0; mi < 4; mi++)
                ldsm4(af[mi], As + (wm + mi * 16 + (lane & 15)) * APAD + ks * 16 + (lane >> 4) * 8);
#pragma unroll
            for (int nh = 0; nh < 4; nh++)
                ldsm4t(bfr[nh], Bs + (ks * 16 + (lane & 15)) * BPAD + wn + nh * 16 + (lane >> 4) * 8);
#pragma unroll
            for (int mi = 0; mi < 4; mi++)
#pragma unroll
                for (int ni = 0; ni < 8; ni++)
                    mma16816(acc[mi][ni], af[mi],
                             bfr[ni >> 1][(ni & 1) * 2], bfr[ni >> 1][(ni & 1) * 2 + 1]);
        }
    }

    // epilogue
    int r = lane >> 2, c = lane & 3;
#pragma unroll
    for (int mi = 0; mi < 4; mi++) {
#pragma unroll
        for (int r2 = 0; r2 < 2; r2++) {
            int row = bm + wm + mi * 16 + r + r2 * 8;
            int bofs = (row >> 13) * gstride;
#pragma unroll
            for (int ni = 0; ni < 8; ni++) {
                int col = bn + wn + ni * 8 + 2 * c;
                float2 bi = *(const float2*)(bias + col);
                float vx = acc[mi][ni][r2 * 2 + 0] + bi.x;
                float vy = acc[mi][ni][r2 * 2 + 1] + bi.y;
                if (MODE == 1) { vx = gelu_tanh(vx); vy = gelu_tanh(vy); }
                if (MODE == 2) {
                    float2 rr = *(const float2*)(resid + (size_t)row * N + col);
                    vx += rr.x; vy += rr.y;
                }
                if (MODE == 3) {
                    float2 rr = *(const float2*)(resid + (size_t)row * N + col);
                    float2 gg = *(const float2*)(gate + bofs + col);
                    vx = rr.x + vx * gg.x;
                    vy = rr.y + vy * gg.y;
                }
                if (OUTB) {
                    *(bf162*)((bf16*)Cout + (size_t)row * N + col) =
                        __floats2bfloat162_rn(vx, vy);
                } else {
                    float2 v; v.x = vx; v.y = vy;
                    *(float2*)((float*)Cout + (size_t)row * N + col) = v;
                }
            }
        }
    }
}

// ---------------------------------------------------------------------------
// Launch
// ---------------------------------------------------------------------------
extern "C" void kernel_launch(void* const* d_in, const int* in_sizes, int n_in,
                              void* d_out, int out_size)
{
    (void)in_sizes; (void)n_in; (void)out_size;
    const float* x     = (const float*)d_in[0];
    const float* mod   = (const float*)d_in[1];
    const float* ctx   = (const float*)d_in[2];
    const float* mod_w = (const float*)d_in[3];
    const float* mod_b = (const float*)d_in[4];
    const float* n2g   = (const float*)d_in[5];
    const float* n2b   = (const float*)d_in[6];
    const float* qkv_w = (const float*)d_in[7];
    const float* qkv_b = (const float*)d_in[8];
    const float* saow  = (const float*)d_in[9];
    const float* saob  = (const float*)d_in[10];
    const float* q_w   = (const float*)d_in[11];
    const float* q_b   = (const float*)d_in[12];
    const float* kv_w  = (const float*)d_in[13];
    const float* kv_b  = (const float*)d_in[14];
    const float* caow  = (const float*)d_in[15];
    const float* caob  = (const float*)d_in[16];
    const float* w1    = (const float*)d_in[17];
    const float* b1    = (const float*)d_in[18];
    const float* w2    = (const float*)d_in[19];
    const float* b2    = (const float*)d_in[20];
    float* out = (float*)d_out;

    float *sa_, *sh_, *m_, *kv_;
    bf16* wb;
    cudaGetSymbolAddress((void**)&sa_, g_scratch_a);
    cudaGetSymbolAddress((void**)&sh_, g_scratch_h);
    cudaGetSymbolAddress((void**)&m_,  g_mbuf);
    cudaGetSymbolAddress((void**)&kv_, g_kvbuf);
    cudaGetSymbolAddress((void**)&wb,  g_wbuf);

    bf16* qkv_bf    = (bf16*)sa_;                          // BL x 3072
    bf16* q_bf      = (bf16*)sa_;                          // BL x 1024 (aliases qkv)
    bf16* hidden_bf = (bf16*)sa_ + (size_t)BL_ * 3 * C_;   // BL x 4096
    bf16* h_bf      = (bf16*)sh_;                          // BL x 1024
    bf16* kv_bf     = (bf16*)kv_;                          // B x 256 x 2048

    bf16* qkvW = wb;
    bf16* saW  = qkvW + 1024 * 3072;
    bf16* qW   = saW  + 1024 * 1024;
    bf16* kvW  = qW   + 1024 * 1024;
    bf16* caW  = kvW  + 1024 * 2048;
    bf16* w1W  = caW  + 1024 * 1024;
    bf16* w2W  = w1W  + 1024 * 4096;
    bf16* ctxB = w2W  + 4096 * 1024;

    cudaFuncSetAttribute(fattn_kernel<true>,  cudaFuncAttributeMaxDynamicSharedMemorySize, FA_SMEM);
    cudaFuncSetAttribute(fattn_kernel<false>, cudaFuncAttributeMaxDynamicSharedMemorySize, FA_SMEM);
    cudaFuncSetAttribute(tgemm_kernel<0,1>, cudaFuncAttributeMaxDynamicSharedMemorySize, TG_SMEM);
    cudaFuncSetAttribute(tgemm_kernel<1,1>, cudaFuncAttributeMaxDynamicSharedMemorySize, TG_SMEM);
    cudaFuncSetAttribute(tgemm_kernel<2,0>, cudaFuncAttributeMaxDynamicSharedMemorySize, TG_SMEM);
    cudaFuncSetAttribute(tgemm_kernel<3,0>, cudaFuncAttributeMaxDynamicSharedMemorySize, TG_SMEM);

    // 0. weight + ctx conversion to bf16
    f2b_kernel<<<1024 * 3072 / 1024, 256>>>(qkv_w, qkvW, 1024 * 3072);
    f2b_kernel<<<1024 * 1024 / 1024, 256>>>(saow,  saW,  1024 * 1024);
    f2b_kernel<<<1024 * 1024 / 1024, 256>>>(q_w,   qW,   1024 * 1024);
    f2b_kernel<<<1024 * 2048 / 1024, 256>>>(kv_w,  kvW,  1024 * 2048);
    f2b_kernel<<<1024 * 1024 / 1024, 256>>>(caow,  caW,  1024 * 1024);
    f2b_kernel<<<1024 * 4096 / 1024, 256>>>(w1,    w1W,  1024 * 4096);
    f2b_kernel<<<4096 * 1024 / 1024, 256>>>(w2,    w2W,  4096 * 1024);
    f2b_kernel<<<B_ * LCTX * C_ / 1024, 256>>>(ctx, ctxB, B_ * LCTX * C_);

    // 1. modulation vectors
    mod_gemm_kernel<<<dim3(24, 4), 256>>>(mod, mod_w, mod_b, m_);
    // 2. h = LN(x)*(1+sc_msa) + sh_msa   -> bf16
    ln_kernel<<<BL_, 256>>>(x, h_bf, m_ + C_, m_, SIXC, 1.0f);
    // 3. qkv = h @ qkv_w + b  -> bf16
    tgemm_kernel<0,1><<<dim3(12, 256), 256, TG_SMEM>>>(h_bf, qkvW, qkv_b, nullptr, nullptr,
                                                       qkv_bf, BL_, 3 * C_, C_, 0);
    // 4. windowed self-attention (MMA flash, rolls folded) -> bf16
    fattn_kernel<true><<<dim3(16, 32, 4), 256, FA_SMEM>>>(
        qkv_bf, qkv_bf + C_, qkv_bf + 2 * C_, h_bf,
        (size_t)L_ * 3 * C_, 3 * C_, (size_t)L_ * 3 * C_, 3 * C_);
    // 5. out = x + (o @ sa_out_w + b) * g_msa   (fp32)
    tgemm_kernel<3,0><<<dim3(4, 256), 256, TG_SMEM>>>(h_bf, saW, saob, x, m_ + 2 * C_,
                                                      out, BL_, C_, C_, SIXC);
    // 6. h2 = LN(out)*norm2_g + norm2_b -> bf16
    ln_kernel<<<BL_, 256>>>(out, h_bf, n2g, n2b, 0, 0.0f);
    // 7. q = h2 @ q_w + b -> bf16
    tgemm_kernel<0,1><<<dim3(4, 256), 256, TG_SMEM>>>(h_bf, qW, q_b, nullptr, nullptr,
                                                      q_bf, BL_, C_, C_, 0);
    // 8. kv = ctx @ kv_w + b -> bf16
    tgemm_kernel<0,1><<<dim3(8, 8), 256, TG_SMEM>>>(ctxB, kvW, kv_b, nullptr, nullptr,
                                                    kv_bf, B_ * LCTX, 2 * C_, C_, 0);
    // 9. cross-attention (MMA flash) -> bf16
    fattn_kernel<false><<<dim3(16, 32, 4), 256, FA_SMEM>>>(
        q_bf, kv_bf, kv_bf + C_, h_bf,
        (size_t)L_ * C_, C_, (size_t)LCTX * 2 * C_, 2 * C_);
    // 10. out += o @ ca_out_w + b  (fp32)
    tgemm_kernel<2,0><<<dim3(4, 256), 256, TG_SMEM>>>(h_bf, caW, caob, out, nullptr,
                                                      out, BL_, C_, C_, 0);
    // 11. h = LN(out)*(1+sc_mlp) + sh_mlp -> bf16
    ln_kernel<<<BL_, 256>>>(out, h_bf, m_ + 4 * C_, m_ + 3 * C_, SIXC, 1.0f);
    // 12. u = gelu(h @ w1 + b1) -> bf16
    tgemm_kernel<1,1><<<dim3(16, 256), 256, TG_SMEM>>>(h_bf, w1W, b1, nullptr, nullptr,
                                                       hidden_bf, BL_, MLP_, C_, 0);
    // 13. out += (u @ w2 + b2) * g_mlp  (fp32)
    tgemm_kernel<3,0><<<dim3(4, 256), 256, TG_SMEM>>>(hidden_bf, w2W, b2, out, m_ + 5 * C_,
                                                      out, BL_, C_, MLP_, SIXC);
}